// round 7
// baseline (speedup 1.0000x reference)
#include <cuda_runtime.h>
#include <cuda_bf16.h>
#include <math.h>
#include <stdint.h>

#define B_ROWS 16384
#define IN1    256
#define HD     512
#define NB     16
#define NPART  1024
#define K1     (IN1 * NB)   // 4096
#define K2     (HD * NB)    // 8192

// GEMM tiling: CTA 128x128, 4 warps (2x2), warp tile 64x64, BK=64, 3 stages
#define BM 128
#define BN 128
#define BK 64
#define NSTAGE 3
#define ST_AH 0
#define ST_AL 16384
#define ST_BH 32768
#define ST_BL 49152
#define STAGE_BYTES 65536
#define GEMM_SMEM (NSTAGE * STAGE_BYTES)   // 192 KB

// ---------------- scratch (device globals) -----------------------------------
__device__ float g_mu1[IN1], g_inv1[IN1];
__device__ float g_mu2[HD],  g_inv2[HD];
__device__ float g_mu3[HD],  g_inv3[HD];
__device__ float g_ps[NPART * HD];
__device__ float g_pq[NPART * HD];
__device__ __align__(128) __nv_bfloat16 g_Ah[(size_t)B_ROWS * K2];
__device__ __align__(128) __nv_bfloat16 g_Al[(size_t)B_ROWS * K2];
__device__ __align__(128) __nv_bfloat16 g_cb1h[(size_t)HD * K1];
__device__ __align__(128) __nv_bfloat16 g_cb1l[(size_t)HD * K1];
__device__ __align__(128) __nv_bfloat16 g_cb2h[(size_t)HD * K2];
__device__ __align__(128) __nv_bfloat16 g_cb2l[(size_t)HD * K2];
__device__ float  g_h1[(size_t)B_ROWS * HD];
__device__ float  g_h2[(size_t)B_ROWS * HD];
__device__ float  g_cp3[HD * NB];
__device__ float2 g_tr[(size_t)B_ROWS * HD];

// ---------------- PTX helpers --------------------------------------------------
__device__ __forceinline__ uint32_t smem_u32(const void* p) {
    uint32_t a;
    asm("{ .reg .u64 t; cvta.to.shared.u64 t, %1; cvt.u32.u64 %0, t; }" : "=r"(a) : "l"(p));
    return a;
}
__device__ __forceinline__ uint32_t sw128(uint32_t b) { return b ^ ((b >> 3) & 0x70u); }
__device__ __forceinline__ void cp16(uint32_t s, const void* g) {
    asm volatile("cp.async.cg.shared.global [%0], [%1], 16;" :: "r"(s), "l"(g));
}
#define CP_COMMIT() asm volatile("cp.async.commit_group;" ::: "memory")

__device__ __forceinline__ void ldmx4(uint32_t* r, uint32_t addr) {
    asm volatile("ldmatrix.sync.aligned.m8n8.x4.shared.b16 {%0,%1,%2,%3}, [%4];"
        : "=r"(r[0]), "=r"(r[1]), "=r"(r[2]), "=r"(r[3]) : "r"(addr));
}
__device__ __forceinline__ void mma16816(float* c, const uint32_t* a, const uint32_t* b) {
    asm volatile("mma.sync.aligned.m16n8k16.row.col.f32.bf16.bf16.f32 "
        "{%0,%1,%2,%3}, {%4,%5,%6,%7}, {%8,%9}, {%0,%1,%2,%3};"
        : "+f"(c[0]), "+f"(c[1]), "+f"(c[2]), "+f"(c[3])
        : "r"(a[0]), "r"(a[1]), "r"(a[2]), "r"(a[3]), "r"(b[0]), "r"(b[1]));
}

// ---------------- stats core ----------------------------------------------------
__device__ __forceinline__ void stats_part_body(const float* __restrict__ src, int C,
                                                int bid, int tid) {
    const int rows = B_ROWS / NPART;   // 16
    const int r0 = bid * rows;
    float s[2] = {0.f, 0.f}, q[2] = {0.f, 0.f};
    const int ncc = C >> 8;
    for (int rr = 0; rr < rows; rr++) {
        const float* row = src + (size_t)(r0 + rr) * C;
        for (int cc = 0; cc < ncc; cc++) {
            float v = row[tid + (cc << 8)];
            s[cc] += v;
            q[cc] = fmaf(v, v, q[cc]);
        }
    }
    for (int cc = 0; cc < ncc; cc++) {
        g_ps[bid * C + tid + (cc << 8)] = s[cc];
        g_pq[bid * C + tid + (cc << 8)] = q[cc];
    }
}

__global__ void k_stats_part(const float* __restrict__ src, int C) {
    stats_part_body(src, C, blockIdx.x, threadIdx.x);
}

__global__ void k_stats_fin(int C, float* __restrict__ mu, float* __restrict__ inv) {
    int c = blockIdx.x * blockDim.x + threadIdx.x;
    if (c >= C) return;
    float s = 0.f, q = 0.f;
    for (int k = 0; k < NPART; k++) { s += g_ps[k * C + c]; q += g_pq[k * C + c]; }
    float m = s / (float)B_ROWS;
    float var = (q - s * m) / (float)(B_ROWS - 1);
    float sd = sqrtf(fmaxf(var, 0.f));
    mu[c] = m;
    inv[c] = 1.f / (sd + 1e-6f);
}

// ---------------- coeff split core ----------------------------------------------
__device__ __forceinline__ void coeff_split_body(const float* __restrict__ src, int K,
        __nv_bfloat16* __restrict__ Bh, __nv_bfloat16* __restrict__ Bl, int o, int tid) {
    for (int k = tid; k < K; k += 256) {
        int n = k & 15;
        float cn = fmaf((float)n, 4.f / 15.f, -2.f);
        float Kn = expf(-2.f * cn * cn);
        float v = src[(size_t)o * K + k] * Kn;
        __nv_bfloat16 h = __float2bfloat16(v);
        float lo = v - __bfloat162float(h);
        Bh[(size_t)o * K + k] = h;
        Bl[(size_t)o * K + k] = __float2bfloat16(lo);
    }
}

// fused: stats_part(x) + coeff_split(c1) + coeff_split(c2) + coeffs3
__global__ void k_prep0(const float* __restrict__ x,
                        const float* __restrict__ c1, const float* __restrict__ c2,
                        const float* __restrict__ c3,
                        __nv_bfloat16* __restrict__ cb1h, __nv_bfloat16* __restrict__ cb1l,
                        __nv_bfloat16* __restrict__ cb2h, __nv_bfloat16* __restrict__ cb2l,
                        float* __restrict__ cp3) {
    int bid = blockIdx.x, tid = threadIdx.x;
    if (bid < NPART) {
        stats_part_body(x, IN1, bid, tid);
    } else if (bid < NPART + HD) {
        coeff_split_body(c1, K1, cb1h, cb1l, bid - NPART, tid);
    } else if (bid < NPART + 2 * HD) {
        coeff_split_body(c2, K2, cb2h, cb2l, bid - NPART - HD, tid);
    } else {
        // c3 transform: dst[i*16 + j] = c3[i*16 + (15-j)] * K_(15-j)
        for (int w = tid; w < HD * NB; w += 256) {
            int i = w >> 4, j = w & 15;
            int n = 15 - j;
            float cn = fmaf((float)n, 4.f / 15.f, -2.f);
            float Kn = expf(-2.f * cn * cn);
            cp3[i * NB + j] = c3[(size_t)i * NB + n] * Kn;
        }
    }
}

// ---------------- basis materialization (bf16 hi/lo, Kn excluded) --------------
__global__ void k_basis(const float* __restrict__ src, const float* __restrict__ mu,
                        const float* __restrict__ inv, int cmask,
                        __nv_bfloat16* __restrict__ Ah, __nv_bfloat16* __restrict__ Al) {
    int idx = blockIdx.x * blockDim.x + threadIdx.x;   // one per (b, i)
    int i = idx & cmask;
    float xn = (src[idx] - mu[i]) * inv[i];
    xn = fminf(3.f, fmaxf(-3.f, xn));
    float t = __expf(fmaf(-2.f * xn, xn, -8.f * xn));
    float r = __expf(xn * (16.f / 15.f));
    unsigned hh[8], ll[8];
    float pv = t;
#pragma unroll
    for (int j = 0; j < 8; j++) {
        float a = pv;
        float b = pv * r;
        pv = b * r;
        __nv_bfloat16 ha = __float2bfloat16(a), hb = __float2bfloat16(b);
        float la = a - __bfloat162float(ha);
        float lb = b - __bfloat162float(hb);
        __nv_bfloat16 lla = __float2bfloat16(la), llb = __float2bfloat16(lb);
        hh[j] = (unsigned)__bfloat16_as_ushort(ha) | ((unsigned)__bfloat16_as_ushort(hb) << 16);
        ll[j] = (unsigned)__bfloat16_as_ushort(lla) | ((unsigned)__bfloat16_as_ushort(llb) << 16);
    }
    uint4* pH = reinterpret_cast<uint4*>(Ah) + (size_t)idx * 2;
    uint4* pL = reinterpret_cast<uint4*>(Al) + (size_t)idx * 2;
    pH[0] = make_uint4(hh[0], hh[1], hh[2], hh[3]);
    pH[1] = make_uint4(hh[4], hh[5], hh[6], hh[7]);
    pL[0] = make_uint4(ll[0], ll[1], ll[2], ll[3]);
    pL[1] = make_uint4(ll[4], ll[5], ll[6], ll[7]);
}

// ---------------- split-bf16 GEMM via mma.sync + fused tanh --------------------
__device__ __forceinline__ void load_tiles(uint32_t st,
        const __nv_bfloat16* __restrict__ Ah, const __nv_bfloat16* __restrict__ Al,
        const __nv_bfloat16* __restrict__ Bh, const __nv_bfloat16* __restrict__ Bl,
        int bm0, int on0, int k0, int K, int tid) {
#pragma unroll
    for (int q = 0; q < 8; q++) {         // 128 rows x 8 16B-chunks, 128 threads
        int e = tid + (q << 7);
        int row = e >> 3, ch = e & 7;
        uint32_t so = sw128((uint32_t)(row << 7) + (ch << 4));
        size_t ga = (size_t)(bm0 + row) * K + k0 + (ch << 3);
        size_t gb = (size_t)(on0 + row) * K + k0 + (ch << 3);
        cp16(st + ST_AH + so, Ah + ga);
        cp16(st + ST_AL + so, Al + ga);
        cp16(st + ST_BH + so, Bh + gb);
        cp16(st + ST_BL + so, Bl + gb);
    }
}

__global__ void __launch_bounds__(128, 1)
k_gemm(const __nv_bfloat16* __restrict__ Ah, const __nv_bfloat16* __restrict__ Al,
       const __nv_bfloat16* __restrict__ Bh, const __nv_bfloat16* __restrict__ Bl,
       float* __restrict__ out, int K) {
    extern __shared__ __align__(1024) char smem_raw[];
    const uint32_t base = smem_u32(smem_raw);
    const int tid = threadIdx.x;
    const int lane = tid & 31, wid = tid >> 5;
    const int wr = wid & 1, wc = wid >> 1;     // 2x2 warp grid: 64x64 per warp
    const int bm0 = blockIdx.y << 7, on0 = blockIdx.x << 7;
    const int NCH = K >> 6;

    float acc[4][8][4];
#pragma unroll
    for (int mt = 0; mt < 4; mt++)
#pragma unroll
        for (int nt = 0; nt < 8; nt++)
#pragma unroll
            for (int e = 0; e < 4; e++) acc[mt][nt][e] = 0.f;

    // 3-stage ring: chunk c in buffer c%3; prologue fills 0,1 (distance 2)
    load_tiles(base, Ah, Al, Bh, Bl, bm0, on0, 0, K, tid);
    CP_COMMIT();
    load_tiles(base + STAGE_BYTES, Ah, Al, Bh, Bl, bm0, on0, BK, K, tid);
    CP_COMMIT();

    const int g = lane >> 3, lr = lane & 7;
    for (int c = 0; c < NCH; c++) {
        if (c == NCH - 1) asm volatile("cp.async.wait_group 0;" ::: "memory");
        else              asm volatile("cp.async.wait_group 1;" ::: "memory");
        __syncthreads();

        // prefetch chunk c+2 into buffer (c+2)%3 (consumed at iter c-1)
        if (c + 2 < NCH) {
            uint32_t nb = (uint32_t)((c + 2) % 3);
            load_tiles(base + nb * STAGE_BYTES, Ah, Al, Bh, Bl,
                       bm0, on0, (c + 2) << 6, K, tid);
            CP_COMMIT();
        }

        uint32_t st = base + (uint32_t)(c % 3) * STAGE_BYTES;

#pragma unroll
        for (int kk = 0; kk < 4; kk++) {
            uint32_t afh[4][4], afl[4][4];
#pragma unroll
            for (int mt = 0; mt < 4; mt++) {
                int m_local = wr * 64 + mt * 16 + (g & 1) * 8 + lr;
                uint32_t off = sw128((uint32_t)(m_local << 7) + (kk << 5) + ((g >> 1) << 4));
                ldmx4(afh[mt], st + ST_AH + off);
                ldmx4(afl[mt], st + ST_AL + off);
            }
            uint32_t bfh[4][4], bfl[4][4];
#pragma unroll
            for (int n2 = 0; n2 < 4; n2++) {
                int n_local = wc * 64 + n2 * 16 + (g >> 1) * 8 + lr;
                uint32_t off = sw128((uint32_t)(n_local << 7) + (kk << 5) + ((g & 1) << 4));
                ldmx4(bfh[n2], st + ST_BH + off);
                ldmx4(bfl[n2], st + ST_BL + off);
            }
#pragma unroll
            for (int mt = 0; mt < 4; mt++)
#pragma unroll
                for (int nt = 0; nt < 8; nt++) {
                    const uint32_t* B0 = &bfh[nt >> 1][(nt & 1) * 2];
                    const uint32_t* B1 = &bfl[nt >> 1][(nt & 1) * 2];
                    mma16816(acc[mt][nt], afh[mt], B0);
                    mma16816(acc[mt][nt], afh[mt], B1);
                    mma16816(acc[mt][nt], afl[mt], B0);
                }
        }
    }

    // epilogue: tanh + store (C frag: lane l -> rows l/4, l/4+8; cols 2*(l%4)+{0,1})
#pragma unroll
    for (int mt = 0; mt < 4; mt++) {
        int row0 = bm0 + wr * 64 + mt * 16 + (lane >> 2);
#pragma unroll
        for (int nt = 0; nt < 8; nt++) {
            int col = on0 + wc * 64 + nt * 8 + (lane & 3) * 2;
            float2 v0, v1;
            v0.x = tanhf(acc[mt][nt][0]);
            v0.y = tanhf(acc[mt][nt][1]);
            v1.x = tanhf(acc[mt][nt][2]);
            v1.y = tanhf(acc[mt][nt][3]);
            *reinterpret_cast<float2*>(out + (size_t)row0 * HD + col) = v0;
            *reinterpret_cast<float2*>(out + (size_t)(row0 + 8) * HD + col) = v1;
        }
    }
}

// ---------------- layer-3 path (SIMT, tiny) -------------------------------------
__global__ void k_prep_tr(const float* __restrict__ src, const float* __restrict__ mu,
                          const float* __restrict__ inv, int cmask, int total,
                          float2* __restrict__ dst) {
    for (int idx = blockIdx.x * blockDim.x + threadIdx.x; idx < total;
         idx += gridDim.x * blockDim.x) {
        int c = idx & cmask;
        float xn = (src[idx] - mu[c]) * inv[c];
        xn = fminf(3.f, fmaxf(-3.f, xn));
        float t = __expf(fmaf(-2.f * xn, xn, -8.f * xn));
        float r = __expf(xn * (16.f / 15.f));
        dst[idx] = make_float2(t, r);
    }
}

__global__ void k_final(const float2* __restrict__ tr, const float* __restrict__ cp3,
                        const float* __restrict__ x, const float* __restrict__ sw,
                        const float* __restrict__ sb, float* __restrict__ out) {
    int warp = threadIdx.x >> 5, lane = threadIdx.x & 31;
    int b = blockIdx.x * 8 + warp;
    float acc = 0.f;
    for (int i = lane; i < HD; i += 32) {
        float2 v = tr[(size_t)b * HD + i];
        const float* c = &cp3[i * NB];
        float p = c[0];
#pragma unroll
        for (int j = 1; j < NB; j++) p = fmaf(p, v.y, c[j]);
        acc = fmaf(v.x, p, acc);
    }
    for (int cidx = lane; cidx < IN1; cidx += 32)
        acc = fmaf(x[(size_t)b * IN1 + cidx], sw[cidx], acc);
#pragma unroll
    for (int off = 16; off; off >>= 1) acc += __shfl_xor_sync(0xffffffffu, acc, off);
    if (lane == 0) out[b] = acc + sb[0];
}

// ---------------- launch ---------------------------------------------------------
extern "C" void kernel_launch(void* const* d_in, const int* in_sizes, int n_in,
                              void* d_out, int out_size) {
    const float* x  = (const float*)d_in[0];
    const float* c1 = (const float*)d_in[1];
    const float* c2 = (const float*)d_in[2];
    const float* c3 = (const float*)d_in[3];
    const float* sw = (const float*)d_in[4];
    const float* sb = (const float*)d_in[5];
    float* out = (float*)d_out;

    __nv_bfloat16 *Ah, *Al, *cb1h, *cb1l, *cb2h, *cb2l;
    float *h1, *h2, *cp3, *mu1, *inv1, *mu2, *inv2, *mu3, *inv3;
    float2* tr;
    cudaGetSymbolAddress((void**)&Ah,   g_Ah);
    cudaGetSymbolAddress((void**)&Al,   g_Al);
    cudaGetSymbolAddress((void**)&cb1h, g_cb1h);
    cudaGetSymbolAddress((void**)&cb1l, g_cb1l);
    cudaGetSymbolAddress((void**)&cb2h, g_cb2h);
    cudaGetSymbolAddress((void**)&cb2l, g_cb2l);
    cudaGetSymbolAddress((void**)&h1,   g_h1);
    cudaGetSymbolAddress((void**)&h2,   g_h2);
    cudaGetSymbolAddress((void**)&cp3,  g_cp3);
    cudaGetSymbolAddress((void**)&tr,   g_tr);
    cudaGetSymbolAddress((void**)&mu1,  g_mu1);
    cudaGetSymbolAddress((void**)&inv1, g_inv1);
    cudaGetSymbolAddress((void**)&mu2,  g_mu2);
    cudaGetSymbolAddress((void**)&inv2, g_inv2);
    cudaGetSymbolAddress((void**)&mu3,  g_mu3);
    cudaGetSymbolAddress((void**)&inv3, g_inv3);

    cudaFuncSetAttribute(k_gemm, cudaFuncAttributeMaxDynamicSharedMemorySize, GEMM_SMEM);

    // index 0: fused stats(x) + coeff splits + c3 transform
    k_prep0<<<NPART + 2 * HD + 1, 256>>>(x, c1, c2, c3, cb1h, cb1l, cb2h, cb2l, cp3);
    // index 1..3: layer 1 (gemm at our index 3)
    k_stats_fin<<<1, 256>>>(IN1, mu1, inv1);
    k_basis<<<(B_ROWS * IN1) / 256, 256>>>(x, mu1, inv1, IN1 - 1, Ah, Al);
    k_gemm<<<dim3(HD / BN, B_ROWS / BM), 128, GEMM_SMEM>>>(Ah, Al, cb1h, cb1l, h1, K1);

    // layer 2
    k_stats_part<<<NPART, 256>>>(h1, HD);
    k_stats_fin<<<2, 256>>>(HD, mu2, inv2);
    k_basis<<<(B_ROWS * HD) / 256, 256>>>(h1, mu2, inv2, HD - 1, Ah, Al);
    k_gemm<<<dim3(HD / BN, B_ROWS / BM), 128, GEMM_SMEM>>>(Ah, Al, cb2h, cb2l, h2, K2);

    // layer 3 + skip
    k_stats_part<<<NPART, 256>>>(h2, HD);
    k_stats_fin<<<2, 256>>>(HD, mu3, inv3);
    k_prep_tr<<<4096, 256>>>(h2, mu3, inv3, HD - 1, B_ROWS * HD, tr);
    k_final<<<B_ROWS / 8, 256>>>(tr, cp3, x, sw, sb, out);
}

// round 8
// speedup vs baseline: 1.0246x; 1.0246x over previous
#include <cuda_runtime.h>
#include <cuda_bf16.h>
#include <math.h>
#include <stdint.h>

#define B_ROWS 16384
#define IN1    256
#define HD     512
#define NB     16
#define NPART  1024
#define K1     (IN1 * NB)   // 4096
#define K2     (HD * NB)    // 8192

// GEMM tiling: CTA 128x128, 8 warps (2x4), warp tile 64x32, BK=64, 3 stages
#define BM 128
#define BN 128
#define BK 64
#define NSTAGE 3
#define ST_AH 0
#define ST_AL 16384
#define ST_BH 32768
#define ST_BL 49152
#define STAGE_BYTES 65536
#define GEMM_SMEM (NSTAGE * STAGE_BYTES)   // 192 KB

// ---------------- scratch (device globals) -----------------------------------
__device__ float g_mu1[IN1], g_inv1[IN1];
__device__ float g_mu2[HD],  g_inv2[HD];
__device__ float g_mu3[HD],  g_inv3[HD];
__device__ float g_ps[NPART * HD];
__device__ float g_pq[NPART * HD];
__device__ __align__(128) __nv_bfloat16 g_Ah[(size_t)B_ROWS * K2];
__device__ __align__(128) __nv_bfloat16 g_Al[(size_t)B_ROWS * K2];
__device__ __align__(128) __nv_bfloat16 g_cb1h[(size_t)HD * K1];
__device__ __align__(128) __nv_bfloat16 g_cb1l[(size_t)HD * K1];
__device__ __align__(128) __nv_bfloat16 g_cb2h[(size_t)HD * K2];
__device__ __align__(128) __nv_bfloat16 g_cb2l[(size_t)HD * K2];
__device__ float  g_h1[(size_t)B_ROWS * HD];
__device__ float  g_h2[(size_t)B_ROWS * HD];
__device__ float  g_cp3[HD * NB];
__device__ float2 g_tr[(size_t)B_ROWS * HD];

// ---------------- PTX helpers --------------------------------------------------
__device__ __forceinline__ uint32_t smem_u32(const void* p) {
    uint32_t a;
    asm("{ .reg .u64 t; cvta.to.shared.u64 t, %1; cvt.u32.u64 %0, t; }" : "=r"(a) : "l"(p));
    return a;
}
__device__ __forceinline__ uint32_t sw128(uint32_t b) { return b ^ ((b >> 3) & 0x70u); }
__device__ __forceinline__ void cp16(uint32_t s, const void* g) {
    asm volatile("cp.async.cg.shared.global [%0], [%1], 16;" :: "r"(s), "l"(g));
}
#define CP_COMMIT() asm volatile("cp.async.commit_group;" ::: "memory")

__device__ __forceinline__ void ldmx4(uint32_t* r, uint32_t addr) {
    asm volatile("ldmatrix.sync.aligned.m8n8.x4.shared.b16 {%0,%1,%2,%3}, [%4];"
        : "=r"(r[0]), "=r"(r[1]), "=r"(r[2]), "=r"(r[3]) : "r"(addr));
}
__device__ __forceinline__ void mma16816(float* c, const uint32_t* a, const uint32_t* b) {
    asm volatile("mma.sync.aligned.m16n8k16.row.col.f32.bf16.bf16.f32 "
        "{%0,%1,%2,%3}, {%4,%5,%6,%7}, {%8,%9}, {%0,%1,%2,%3};"
        : "+f"(c[0]), "+f"(c[1]), "+f"(c[2]), "+f"(c[3])
        : "r"(a[0]), "r"(a[1]), "r"(a[2]), "r"(a[3]), "r"(b[0]), "r"(b[1]));
}

// ---------------- stats core ----------------------------------------------------
__device__ __forceinline__ void stats_part_body(const float* __restrict__ src, int C,
                                                int bid, int tid) {
    const int rows = B_ROWS / NPART;   // 16
    const int r0 = bid * rows;
    float s[2] = {0.f, 0.f}, q[2] = {0.f, 0.f};
    const int ncc = C >> 8;
    for (int rr = 0; rr < rows; rr++) {
        const float* row = src + (size_t)(r0 + rr) * C;
        for (int cc = 0; cc < ncc; cc++) {
            float v = row[tid + (cc << 8)];
            s[cc] += v;
            q[cc] = fmaf(v, v, q[cc]);
        }
    }
    for (int cc = 0; cc < ncc; cc++) {
        g_ps[bid * C + tid + (cc << 8)] = s[cc];
        g_pq[bid * C + tid + (cc << 8)] = q[cc];
    }
}

__global__ void k_stats_part(const float* __restrict__ src, int C) {
    stats_part_body(src, C, blockIdx.x, threadIdx.x);
}

__global__ void k_stats_fin(int C, float* __restrict__ mu, float* __restrict__ inv) {
    int c = blockIdx.x * blockDim.x + threadIdx.x;
    if (c >= C) return;
    float s = 0.f, q = 0.f;
    for (int k = 0; k < NPART; k++) { s += g_ps[k * C + c]; q += g_pq[k * C + c]; }
    float m = s / (float)B_ROWS;
    float var = (q - s * m) / (float)(B_ROWS - 1);
    float sd = sqrtf(fmaxf(var, 0.f));
    mu[c] = m;
    inv[c] = 1.f / (sd + 1e-6f);
}

// ---------------- coeff split core ----------------------------------------------
__device__ __forceinline__ void coeff_split_body(const float* __restrict__ src, int K,
        __nv_bfloat16* __restrict__ Bh, __nv_bfloat16* __restrict__ Bl, int o, int tid) {
    for (int k = tid; k < K; k += 256) {
        int n = k & 15;
        float cn = fmaf((float)n, 4.f / 15.f, -2.f);
        float Kn = expf(-2.f * cn * cn);
        float v = src[(size_t)o * K + k] * Kn;
        __nv_bfloat16 h = __float2bfloat16(v);
        float lo = v - __bfloat162float(h);
        Bh[(size_t)o * K + k] = h;
        Bl[(size_t)o * K + k] = __float2bfloat16(lo);
    }
}

// fused: stats_part(x) + coeff_split(c1) + coeff_split(c2) + coeffs3
__global__ void k_prep0(const float* __restrict__ x,
                        const float* __restrict__ c1, const float* __restrict__ c2,
                        const float* __restrict__ c3,
                        __nv_bfloat16* __restrict__ cb1h, __nv_bfloat16* __restrict__ cb1l,
                        __nv_bfloat16* __restrict__ cb2h, __nv_bfloat16* __restrict__ cb2l,
                        float* __restrict__ cp3) {
    int bid = blockIdx.x, tid = threadIdx.x;
    if (bid < NPART) {
        stats_part_body(x, IN1, bid, tid);
    } else if (bid < NPART + HD) {
        coeff_split_body(c1, K1, cb1h, cb1l, bid - NPART, tid);
    } else if (bid < NPART + 2 * HD) {
        coeff_split_body(c2, K2, cb2h, cb2l, bid - NPART - HD, tid);
    } else {
        for (int w = tid; w < HD * NB; w += 256) {
            int i = w >> 4, j = w & 15;
            int n = 15 - j;
            float cn = fmaf((float)n, 4.f / 15.f, -2.f);
            float Kn = expf(-2.f * cn * cn);
            cp3[i * NB + j] = c3[(size_t)i * NB + n] * Kn;
        }
    }
}

// ---------------- basis materialization (bf16 hi/lo, Kn excluded) --------------
__global__ void k_basis(const float* __restrict__ src, const float* __restrict__ mu,
                        const float* __restrict__ inv, int cmask,
                        __nv_bfloat16* __restrict__ Ah, __nv_bfloat16* __restrict__ Al) {
    int idx = blockIdx.x * blockDim.x + threadIdx.x;   // one per (b, i)
    int i = idx & cmask;
    float xn = (src[idx] - mu[i]) * inv[i];
    xn = fminf(3.f, fmaxf(-3.f, xn));
    float t = __expf(fmaf(-2.f * xn, xn, -8.f * xn));
    float r = __expf(xn * (16.f / 15.f));
    unsigned hh[8], ll[8];
    float pv = t;
#pragma unroll
    for (int j = 0; j < 8; j++) {
        float a = pv;
        float b = pv * r;
        pv = b * r;
        __nv_bfloat16 ha = __float2bfloat16(a), hb = __float2bfloat16(b);
        float la = a - __bfloat162float(ha);
        float lb = b - __bfloat162float(hb);
        __nv_bfloat16 lla = __float2bfloat16(la), llb = __float2bfloat16(lb);
        hh[j] = (unsigned)__bfloat16_as_ushort(ha) | ((unsigned)__bfloat16_as_ushort(hb) << 16);
        ll[j] = (unsigned)__bfloat16_as_ushort(lla) | ((unsigned)__bfloat16_as_ushort(llb) << 16);
    }
    uint4* pH = reinterpret_cast<uint4*>(Ah) + (size_t)idx * 2;
    uint4* pL = reinterpret_cast<uint4*>(Al) + (size_t)idx * 2;
    pH[0] = make_uint4(hh[0], hh[1], hh[2], hh[3]);
    pH[1] = make_uint4(hh[4], hh[5], hh[6], hh[7]);
    pL[0] = make_uint4(ll[0], ll[1], ll[2], ll[3]);
    pL[1] = make_uint4(ll[4], ll[5], ll[6], ll[7]);
}

// ---------------- split-bf16 GEMM via mma.sync + fused tanh --------------------
__device__ __forceinline__ void load_tiles(uint32_t st,
        const __nv_bfloat16* __restrict__ Ah, const __nv_bfloat16* __restrict__ Al,
        const __nv_bfloat16* __restrict__ Bh, const __nv_bfloat16* __restrict__ Bl,
        int bm0, int on0, int k0, int K, int tid) {
#pragma unroll
    for (int q = 0; q < 4; q++) {         // 128 rows x 8 16B-chunks, 256 threads
        int e = tid + (q << 8);
        int row = e >> 3, ch = e & 7;
        uint32_t so = sw128((uint32_t)(row << 7) + (ch << 4));
        size_t ga = (size_t)(bm0 + row) * K + k0 + (ch << 3);
        size_t gb = (size_t)(on0 + row) * K + k0 + (ch << 3);
        cp16(st + ST_AH + so, Ah + ga);
        cp16(st + ST_AL + so, Al + ga);
        cp16(st + ST_BH + so, Bh + gb);
        cp16(st + ST_BL + so, Bl + gb);
    }
}

// load one kk-step's fragments (A: 64 rows -> 4 m-tiles; B: 32 cols -> 2 n-pairs)
__device__ __forceinline__ void load_frags(uint32_t st, int kk, int wr, int wc,
        int g, int lr,
        uint32_t afh[4][4], uint32_t afl[4][4],
        uint32_t bfh[2][4], uint32_t bfl[2][4]) {
#pragma unroll
    for (int mt = 0; mt < 4; mt++) {
        int m_local = wr * 64 + mt * 16 + (g & 1) * 8 + lr;
        uint32_t off = sw128((uint32_t)(m_local << 7) + (kk << 5) + ((g >> 1) << 4));
        ldmx4(afh[mt], st + ST_AH + off);
        ldmx4(afl[mt], st + ST_AL + off);
    }
#pragma unroll
    for (int n2 = 0; n2 < 2; n2++) {
        int n_local = wc * 32 + n2 * 16 + (g >> 1) * 8 + lr;
        uint32_t off = sw128((uint32_t)(n_local << 7) + (kk << 5) + ((g & 1) << 4));
        ldmx4(bfh[n2], st + ST_BH + off);
        ldmx4(bfl[n2], st + ST_BL + off);
    }
}

__global__ void __launch_bounds__(256, 1)
k_gemm(const __nv_bfloat16* __restrict__ Ah, const __nv_bfloat16* __restrict__ Al,
       const __nv_bfloat16* __restrict__ Bh, const __nv_bfloat16* __restrict__ Bl,
       float* __restrict__ out, int K) {
    extern __shared__ __align__(1024) char smem_raw[];
    const uint32_t base = smem_u32(smem_raw);
    const int tid = threadIdx.x;
    const int lane = tid & 31, wid = tid >> 5;
    const int wr = wid & 1, wc = wid >> 1;     // 2x4 warp grid: 64x32 per warp
    const int bm0 = blockIdx.y << 7, on0 = blockIdx.x << 7;
    const int NCH = K >> 6;

    float acc[4][4][4];
#pragma unroll
    for (int mt = 0; mt < 4; mt++)
#pragma unroll
        for (int nt = 0; nt < 4; nt++)
#pragma unroll
            for (int e = 0; e < 4; e++) acc[mt][nt][e] = 0.f;

    // 3-stage ring: chunk c in buffer c%3; prologue fills 0,1 (distance 2)
    load_tiles(base, Ah, Al, Bh, Bl, bm0, on0, 0, K, tid);
    CP_COMMIT();
    load_tiles(base + STAGE_BYTES, Ah, Al, Bh, Bl, bm0, on0, BK, K, tid);
    CP_COMMIT();

    const int g = lane >> 3, lr = lane & 7;

    // double-buffered fragments across kk
    uint32_t afh[2][4][4], afl[2][4][4], bfh[2][2][4], bfl[2][2][4];

    for (int c = 0; c < NCH; c++) {
        if (c == NCH - 1) asm volatile("cp.async.wait_group 0;" ::: "memory");
        else              asm volatile("cp.async.wait_group 1;" ::: "memory");
        __syncthreads();

        // prefetch chunk c+2 into buffer (c+2)%3 (consumed at iter c-1)
        if (c + 2 < NCH) {
            uint32_t nb = (uint32_t)((c + 2) % 3);
            load_tiles(base + nb * STAGE_BYTES, Ah, Al, Bh, Bl,
                       bm0, on0, (c + 2) << 6, K, tid);
            CP_COMMIT();
        }

        uint32_t st = base + (uint32_t)(c % 3) * STAGE_BYTES;

        load_frags(st, 0, wr, wc, g, lr, afh[0], afl[0], bfh[0], bfl[0]);
#pragma unroll
        for (int kk = 0; kk < 4; kk++) {
            int cur = kk & 1;
            if (kk < 3)
                load_frags(st, kk + 1, wr, wc, g, lr,
                           afh[cur ^ 1], afl[cur ^ 1], bfh[cur ^ 1], bfl[cur ^ 1]);
#pragma unroll
            for (int mt = 0; mt < 4; mt++)
#pragma unroll
                for (int nt = 0; nt < 4; nt++) {
                    const uint32_t* B0 = &bfh[cur][nt >> 1][(nt & 1) * 2];
                    const uint32_t* B1 = &bfl[cur][nt >> 1][(nt & 1) * 2];
                    mma16816(acc[mt][nt], afh[cur][mt], B0);
                    mma16816(acc[mt][nt], afh[cur][mt], B1);
                    mma16816(acc[mt][nt], afl[cur][mt], B0);
                }
        }
    }

    // epilogue: tanh + store (C frag: lane l -> rows l/4, l/4+8; cols 2*(l%4)+{0,1})
#pragma unroll
    for (int mt = 0; mt < 4; mt++) {
        int row0 = bm0 + wr * 64 + mt * 16 + (lane >> 2);
#pragma unroll
        for (int nt = 0; nt < 4; nt++) {
            int col = on0 + wc * 32 + nt * 8 + (lane & 3) * 2;
            float2 v0, v1;
            v0.x = tanhf(acc[mt][nt][0]);
            v0.y = tanhf(acc[mt][nt][1]);
            v1.x = tanhf(acc[mt][nt][2]);
            v1.y = tanhf(acc[mt][nt][3]);
            *reinterpret_cast<float2*>(out + (size_t)row0 * HD + col) = v0;
            *reinterpret_cast<float2*>(out + (size_t)(row0 + 8) * HD + col) = v1;
        }
    }
}

// ---------------- layer-3 path (SIMT, tiny) -------------------------------------
__global__ void k_prep_tr(const float* __restrict__ src, const float* __restrict__ mu,
                          const float* __restrict__ inv, int cmask, int total,
                          float2* __restrict__ dst) {
    for (int idx = blockIdx.x * blockDim.x + threadIdx.x; idx < total;
         idx += gridDim.x * blockDim.x) {
        int c = idx & cmask;
        float xn = (src[idx] - mu[c]) * inv[c];
        xn = fminf(3.f, fmaxf(-3.f, xn));
        float t = __expf(fmaf(-2.f * xn, xn, -8.f * xn));
        float r = __expf(xn * (16.f / 15.f));
        dst[idx] = make_float2(t, r);
    }
}

__global__ void k_final(const float2* __restrict__ tr, const float* __restrict__ cp3,
                        const float* __restrict__ x, const float* __restrict__ sw,
                        const float* __restrict__ sb, float* __restrict__ out) {
    int warp = threadIdx.x >> 5, lane = threadIdx.x & 31;
    int b = blockIdx.x * 8 + warp;
    float acc = 0.f;
    for (int i = lane; i < HD; i += 32) {
        float2 v = tr[(size_t)b * HD + i];
        const float* c = &cp3[i * NB];
        float p = c[0];
#pragma unroll
        for (int j = 1; j < NB; j++) p = fmaf(p, v.y, c[j]);
        acc = fmaf(v.x, p, acc);
    }
    for (int cidx = lane; cidx < IN1; cidx += 32)
        acc = fmaf(x[(size_t)b * IN1 + cidx], sw[cidx], acc);
#pragma unroll
    for (int off = 16; off; off >>= 1) acc += __shfl_xor_sync(0xffffffffu, acc, off);
    if (lane == 0) out[b] = acc + sb[0];
}

// ---------------- launch ---------------------------------------------------------
extern "C" void kernel_launch(void* const* d_in, const int* in_sizes, int n_in,
                              void* d_out, int out_size) {
    const float* x  = (const float*)d_in[0];
    const float* c1 = (const float*)d_in[1];
    const float* c2 = (const float*)d_in[2];
    const float* c3 = (const float*)d_in[3];
    const float* sw = (const float*)d_in[4];
    const float* sb = (const float*)d_in[5];
    float* out = (float*)d_out;

    __nv_bfloat16 *Ah, *Al, *cb1h, *cb1l, *cb2h, *cb2l;
    float *h1, *h2, *cp3, *mu1, *inv1, *mu2, *inv2, *mu3, *inv3;
    float2* tr;
    cudaGetSymbolAddress((void**)&Ah,   g_Ah);
    cudaGetSymbolAddress((void**)&Al,   g_Al);
    cudaGetSymbolAddress((void**)&cb1h, g_cb1h);
    cudaGetSymbolAddress((void**)&cb1l, g_cb1l);
    cudaGetSymbolAddress((void**)&cb2h, g_cb2h);
    cudaGetSymbolAddress((void**)&cb2l, g_cb2l);
    cudaGetSymbolAddress((void**)&h1,   g_h1);
    cudaGetSymbolAddress((void**)&h2,   g_h2);
    cudaGetSymbolAddress((void**)&cp3,  g_cp3);
    cudaGetSymbolAddress((void**)&tr,   g_tr);
    cudaGetSymbolAddress((void**)&mu1,  g_mu1);
    cudaGetSymbolAddress((void**)&inv1, g_inv1);
    cudaGetSymbolAddress((void**)&mu2,  g_mu2);
    cudaGetSymbolAddress((void**)&inv2, g_inv2);
    cudaGetSymbolAddress((void**)&mu3,  g_mu3);
    cudaGetSymbolAddress((void**)&inv3, g_inv3);

    cudaFuncSetAttribute(k_gemm, cudaFuncAttributeMaxDynamicSharedMemorySize, GEMM_SMEM);

    // index 0: fused stats(x) + coeff splits + c3 transform
    k_prep0<<<NPART + 2 * HD + 1, 256>>>(x, c1, c2, c3, cb1h, cb1l, cb2h, cb2l, cp3);
    // layer 1 (gemm at launch index 3 for the ncu window)
    k_stats_fin<<<1, 256>>>(IN1, mu1, inv1);
    k_basis<<<(B_ROWS * IN1) / 256, 256>>>(x, mu1, inv1, IN1 - 1, Ah, Al);
    k_gemm<<<dim3(HD / BN, B_ROWS / BM), 256, GEMM_SMEM>>>(Ah, Al, cb1h, cb1l, h1, K1);

    // layer 2
    k_stats_part<<<NPART, 256>>>(h1, HD);
    k_stats_fin<<<2, 256>>>(HD, mu2, inv2);
    k_basis<<<(B_ROWS * HD) / 256, 256>>>(h1, mu2, inv2, HD - 1, Ah, Al);
    k_gemm<<<dim3(HD / BN, B_ROWS / BM), 256, GEMM_SMEM>>>(Ah, Al, cb2h, cb2l, h2, K2);

    // layer 3 + skip
    k_stats_part<<<NPART, 256>>>(h2, HD);
    k_stats_fin<<<2, 256>>>(HD, mu3, inv3);
    k_prep_tr<<<4096, 256>>>(h2, mu3, inv3, HD - 1, B_ROWS * HD, tr);
    k_final<<<B_ROWS / 8, 256>>>(tr, cp3, x, sw, sb, out);
}

// round 9
// speedup vs baseline: 1.0919x; 1.0656x over previous
#include <cuda_runtime.h>
#include <cuda_bf16.h>
#include <math.h>
#include <stdint.h>

#define B_ROWS 16384
#define IN1    256
#define HD     512
#define NB     16
#define NPART  1024
#define K1     (IN1 * NB)   // 4096
#define K2     (HD * NB)    // 8192

// GEMM: CTA 128x128, 8 warps (2x4), warp tile 64x32, BK=64
// SMEM: A double-buffer (gen'd in-kernel) + 3-stage B ring + 3-slot src ring
#define BM 128
#define BN 128
#define BK 64
#define AB_BYTES   32768                    // per A buffer: hi 16K + lo 16K
#define AB_LO      16384
#define B_BASE     65536                    // after 2 A buffers
#define B_STAGE    32768                    // hi 16K + lo 16K
#define B_LO       16384
#define SRC_BASE   (B_BASE + 3 * B_STAGE)   // 163840
#define SRC_SLOT   2048
#define GEMM_SMEM  (SRC_BASE + 3 * SRC_SLOT)  // 169984

// ---------------- scratch (device globals) -----------------------------------
__device__ float g_mu1[IN1], g_inv1[IN1];
__device__ float g_mu2[HD],  g_inv2[HD];
__device__ float g_mu3[HD],  g_inv3[HD];
__device__ float g_ps[NPART * HD];
__device__ float g_pq[NPART * HD];
__device__ __align__(128) __nv_bfloat16 g_cb1h[(size_t)HD * K1];
__device__ __align__(128) __nv_bfloat16 g_cb1l[(size_t)HD * K1];
__device__ __align__(128) __nv_bfloat16 g_cb2h[(size_t)HD * K2];
__device__ __align__(128) __nv_bfloat16 g_cb2l[(size_t)HD * K2];
__device__ float  g_h1[(size_t)B_ROWS * HD];
__device__ float  g_h2[(size_t)B_ROWS * HD];
__device__ float  g_cp3[HD * NB];
__device__ float2 g_tr[(size_t)B_ROWS * HD];

// ---------------- PTX helpers --------------------------------------------------
__device__ __forceinline__ uint32_t smem_u32(const void* p) {
    uint32_t a;
    asm("{ .reg .u64 t; cvta.to.shared.u64 t, %1; cvt.u32.u64 %0, t; }" : "=r"(a) : "l"(p));
    return a;
}
__device__ __forceinline__ uint32_t sw128(uint32_t b) { return b ^ ((b >> 3) & 0x70u); }
__device__ __forceinline__ void cp16(uint32_t s, const void* g) {
    asm volatile("cp.async.cg.shared.global [%0], [%1], 16;" :: "r"(s), "l"(g));
}
#define CP_COMMIT() asm volatile("cp.async.commit_group;" ::: "memory")

__device__ __forceinline__ void ldmx4(uint32_t* r, uint32_t addr) {
    asm volatile("ldmatrix.sync.aligned.m8n8.x4.shared.b16 {%0,%1,%2,%3}, [%4];"
        : "=r"(r[0]), "=r"(r[1]), "=r"(r[2]), "=r"(r[3]) : "r"(addr));
}
__device__ __forceinline__ void mma16816(float* c, const uint32_t* a, const uint32_t* b) {
    asm volatile("mma.sync.aligned.m16n8k16.row.col.f32.bf16.bf16.f32 "
        "{%0,%1,%2,%3}, {%4,%5,%6,%7}, {%8,%9}, {%0,%1,%2,%3};"
        : "+f"(c[0]), "+f"(c[1]), "+f"(c[2]), "+f"(c[3])
        : "r"(a[0]), "r"(a[1]), "r"(a[2]), "r"(a[3]), "r"(b[0]), "r"(b[1]));
}
// packs (lo, hi) floats into bf16x2 word, lo at low half (RN)
__device__ __forceinline__ uint32_t bf16pack(float lo, float hi) {
    uint32_t w;
    asm("cvt.rn.bf16x2.f32 %0, %1, %2;" : "=r"(w) : "f"(hi), "f"(lo));
    return w;
}

// ---------------- stats core ----------------------------------------------------
__device__ __forceinline__ void stats_part_body(const float* __restrict__ src, int C,
                                                int bid, int tid) {
    const int rows = B_ROWS / NPART;   // 16
    const int r0 = bid * rows;
    float s[2] = {0.f, 0.f}, q[2] = {0.f, 0.f};
    const int ncc = C >> 8;
    for (int rr = 0; rr < rows; rr++) {
        const float* row = src + (size_t)(r0 + rr) * C;
        for (int cc = 0; cc < ncc; cc++) {
            float v = row[tid + (cc << 8)];
            s[cc] += v;
            q[cc] = fmaf(v, v, q[cc]);
        }
    }
    for (int cc = 0; cc < ncc; cc++) {
        g_ps[bid * C + tid + (cc << 8)] = s[cc];
        g_pq[bid * C + tid + (cc << 8)] = q[cc];
    }
}

__global__ void k_stats_part(const float* __restrict__ src, int C) {
    stats_part_body(src, C, blockIdx.x, threadIdx.x);
}

__global__ void k_stats_fin(int C, float* __restrict__ mu, float* __restrict__ inv) {
    int c = blockIdx.x * blockDim.x + threadIdx.x;
    if (c >= C) return;
    float s = 0.f, q = 0.f;
    for (int k = 0; k < NPART; k++) { s += g_ps[k * C + c]; q += g_pq[k * C + c]; }
    float m = s / (float)B_ROWS;
    float var = (q - s * m) / (float)(B_ROWS - 1);
    float sd = sqrtf(fmaxf(var, 0.f));
    mu[c] = m;
    inv[c] = 1.f / (sd + 1e-6f);
}

// ---------------- coeff split core ----------------------------------------------
__device__ __forceinline__ void coeff_split_body(const float* __restrict__ src, int K,
        __nv_bfloat16* __restrict__ Bh, __nv_bfloat16* __restrict__ Bl, int o, int tid) {
    for (int k = tid; k < K; k += 256) {
        int n = k & 15;
        float cn = fmaf((float)n, 4.f / 15.f, -2.f);
        float Kn = expf(-2.f * cn * cn);
        float v = src[(size_t)o * K + k] * Kn;
        __nv_bfloat16 h = __float2bfloat16(v);
        float lo = v - __bfloat162float(h);
        Bh[(size_t)o * K + k] = h;
        Bl[(size_t)o * K + k] = __float2bfloat16(lo);
    }
}

// fused: stats_part(x) + coeff_split(c1) + coeffs3
__global__ void k_prep0a(const float* __restrict__ x, const float* __restrict__ c1,
                         const float* __restrict__ c3,
                         __nv_bfloat16* __restrict__ cb1h, __nv_bfloat16* __restrict__ cb1l,
                         float* __restrict__ cp3) {
    int bid = blockIdx.x, tid = threadIdx.x;
    if (bid < NPART) {
        stats_part_body(x, IN1, bid, tid);
    } else if (bid < NPART + HD) {
        coeff_split_body(c1, K1, cb1h, cb1l, bid - NPART, tid);
    } else {
        for (int w = tid; w < HD * NB; w += 256) {
            int i = w >> 4, j = w & 15;
            int n = 15 - j;
            float cn = fmaf((float)n, 4.f / 15.f, -2.f);
            float Kn = expf(-2.f * cn * cn);
            cp3[i * NB + j] = c3[(size_t)i * NB + n] * Kn;
        }
    }
}

__global__ void k_csplit2(const float* __restrict__ c2,
                          __nv_bfloat16* __restrict__ cb2h, __nv_bfloat16* __restrict__ cb2l) {
    coeff_split_body(c2, K2, cb2h, cb2l, blockIdx.x, threadIdx.x);
}

// ---------------- fused basis-gen + split-bf16 GEMM + tanh ----------------------
__device__ __forceinline__ void load_B(uint32_t stage_base,
        const __nv_bfloat16* __restrict__ Bh, const __nv_bfloat16* __restrict__ Bl,
        int on0, int k0, int K, int tid) {
#pragma unroll
    for (int q = 0; q < 4; q++) {          // 128 rows x 8 16B-chunks, 256 threads
        int e = tid + (q << 8);
        int row = e >> 3, ch = e & 7;
        uint32_t so = sw128((uint32_t)(row << 7) + (ch << 4));
        size_t gb = (size_t)(on0 + row) * K + k0 + (ch << 3);
        cp16(stage_base + so, Bh + gb);
        cp16(stage_base + B_LO + so, Bl + gb);
    }
}

// expand one (row, icol) pair of the NEXT chunk into swizzled A-tile (hi/lo bf16)
__device__ __forceinline__ void gen_pair(char* smem, int p, uint32_t src_slot,
        uint32_t abuf, int i0, const float* __restrict__ mu,
        const float* __restrict__ inv) {
    int row = p >> 2, icol = p & 3;
    float v = reinterpret_cast<const float*>(smem + SRC_BASE + src_slot * SRC_SLOT)
                  [(row << 2) + icol];
    int i = i0 + icol;
    float xn = (v - __ldg(mu + i)) * __ldg(inv + i);
    xn = fminf(3.f, fmaxf(-3.f, xn));
    float t = __expf(fmaf(-2.f * xn, xn, -8.f * xn));
    float r = __expf(xn * (16.f / 15.f));
    uint32_t wh[8], wl[8];
    float pv = t;
#pragma unroll
    for (int m = 0; m < 8; m++) {
        float p0 = pv;
        float p1 = pv * r;
        pv = p1 * r;
        uint32_t w = bf16pack(p0, p1);
        wh[m] = w;
        float h0 = __uint_as_float(w << 16);
        float h1 = __uint_as_float(w & 0xffff0000u);
        wl[m] = bf16pack(p0 - h0, p1 - h1);
    }
    uint32_t base = (uint32_t)(row << 7) + (icol << 5);
    uint32_t a0 = sw128(base), a1 = sw128(base + 16);
    *reinterpret_cast<uint4*>(smem + abuf + a0) = make_uint4(wh[0], wh[1], wh[2], wh[3]);
    *reinterpret_cast<uint4*>(smem + abuf + a1) = make_uint4(wh[4], wh[5], wh[6], wh[7]);
    *reinterpret_cast<uint4*>(smem + abuf + AB_LO + a0) = make_uint4(wl[0], wl[1], wl[2], wl[3]);
    *reinterpret_cast<uint4*>(smem + abuf + AB_LO + a1) = make_uint4(wl[4], wl[5], wl[6], wl[7]);
}

__global__ void __launch_bounds__(256, 1)
k_gemm(const float* __restrict__ src, const float* __restrict__ mu,
       const float* __restrict__ inv,
       const __nv_bfloat16* __restrict__ Bh, const __nv_bfloat16* __restrict__ Bl,
       float* __restrict__ out, int K, int C) {
    extern __shared__ __align__(1024) char smem_raw[];
    const uint32_t base = smem_u32(smem_raw);
    const int tid = threadIdx.x;
    const int lane = tid & 31, wid = tid >> 5;
    const int wr = wid & 1, wc = wid >> 1;     // 2x4 warp grid: 64x32 per warp
    const int bm0 = blockIdx.y << 7, on0 = blockIdx.x << 7;
    const int NCH = K >> 6;

    float acc[4][4][4];
#pragma unroll
    for (int mt = 0; mt < 4; mt++)
#pragma unroll
        for (int nt = 0; nt < 4; nt++)
#pragma unroll
            for (int e = 0; e < 4; e++) acc[mt][nt][e] = 0.f;

    // prologue: commit B+src for chunks 0,1 (one group each)
    load_B(base + B_BASE, Bh, Bl, on0, 0, K, tid);
    if (tid < 128) cp16(base + SRC_BASE + (tid << 4),
                        src + (size_t)(bm0 + tid) * C);
    CP_COMMIT();
    load_B(base + B_BASE + B_STAGE, Bh, Bl, on0, BK, K, tid);
    if (tid < 128) cp16(base + SRC_BASE + SRC_SLOT + (tid << 4),
                        src + (size_t)(bm0 + tid) * C + 4);
    CP_COMMIT();
    asm volatile("cp.async.wait_group 1;" ::: "memory");   // group 0 done
    __syncthreads();
    // gen chunk 0 into A buffer 0
    gen_pair(smem_raw, tid * 2,     0, 0, 0, mu, inv);
    gen_pair(smem_raw, tid * 2 + 1, 0, 0, 0, mu, inv);

    const int g = lane >> 3, lr = lane & 7;

    for (int c = 0; c < NCH; c++) {
        asm volatile("cp.async.wait_group 0;" ::: "memory");  // groups <= c+1 done
        __syncthreads();   // visibility of cp(src c+1, B c+1) + gen(c) + frees stage (c+2)%3

        if (c + 2 < NCH) {
            int s = (c + 2) % 3;
            load_B(base + B_BASE + (uint32_t)s * B_STAGE, Bh, Bl, on0, (c + 2) << 6, K, tid);
            if (tid < 128) cp16(base + SRC_BASE + (uint32_t)s * SRC_SLOT + (tid << 4),
                                src + (size_t)(bm0 + tid) * C + ((c + 2) << 2));
            CP_COMMIT();
        }

        const uint32_t abuf = (uint32_t)(c & 1) * AB_BYTES;
        const uint32_t bst  = B_BASE + (uint32_t)(c % 3) * B_STAGE;
        const bool do_gen = (c + 1 < NCH);
        const uint32_t gslot = (uint32_t)((c + 1) % 3);
        const uint32_t gbuf = (uint32_t)((c + 1) & 1) * AB_BYTES;
        const int gi0 = (c + 1) << 2;

#pragma unroll
        for (int kk = 0; kk < 4; kk++) {
            uint32_t afh[4][4], afl[4][4];
#pragma unroll
            for (int mt = 0; mt < 4; mt++) {
                int m_local = wr * 64 + mt * 16 + (g & 1) * 8 + lr;
                uint32_t off = sw128((uint32_t)(m_local << 7) + (kk << 5) + ((g >> 1) << 4));
                ldmx4(afh[mt], base + abuf + off);
                ldmx4(afl[mt], base + abuf + AB_LO + off);
            }
            uint32_t bfh[2][4], bfl[2][4];
#pragma unroll
            for (int n2 = 0; n2 < 2; n2++) {
                int n_local = wc * 32 + n2 * 16 + (g >> 1) * 8 + lr;
                uint32_t off = sw128((uint32_t)(n_local << 7) + (kk << 5) + ((g & 1) << 4));
                ldmx4(bfh[n2], base + bst + off);
                ldmx4(bfl[n2], base + bst + B_LO + off);
            }
#pragma unroll
            for (int mt = 0; mt < 4; mt++)
#pragma unroll
                for (int nt = 0; nt < 4; nt++) {
                    const uint32_t* B0 = &bfh[nt >> 1][(nt & 1) * 2];
                    const uint32_t* B1 = &bfl[nt >> 1][(nt & 1) * 2];
                    mma16816(acc[mt][nt], afh[mt], B0);
                    mma16816(acc[mt][nt], afh[mt], B1);
                    mma16816(acc[mt][nt], afl[mt], B0);
                }
            if (kk == 1 && do_gen) gen_pair(smem_raw, tid * 2,     gslot, gbuf, gi0, mu, inv);
            if (kk == 3 && do_gen) gen_pair(smem_raw, tid * 2 + 1, gslot, gbuf, gi0, mu, inv);
        }
    }

    // epilogue: tanh + store
#pragma unroll
    for (int mt = 0; mt < 4; mt++) {
        int row0 = bm0 + wr * 64 + mt * 16 + (lane >> 2);
#pragma unroll
        for (int nt = 0; nt < 4; nt++) {
            int col = on0 + wc * 32 + nt * 8 + (lane & 3) * 2;
            float2 v0, v1;
            v0.x = tanhf(acc[mt][nt][0]);
            v0.y = tanhf(acc[mt][nt][1]);
            v1.x = tanhf(acc[mt][nt][2]);
            v1.y = tanhf(acc[mt][nt][3]);
            *reinterpret_cast<float2*>(out + (size_t)row0 * HD + col) = v0;
            *reinterpret_cast<float2*>(out + (size_t)(row0 + 8) * HD + col) = v1;
        }
    }
}

// ---------------- layer-3 path (SIMT, tiny) -------------------------------------
__global__ void k_prep_tr(const float* __restrict__ src, const float* __restrict__ mu,
                          const float* __restrict__ inv, int cmask, int total,
                          float2* __restrict__ dst) {
    for (int idx = blockIdx.x * blockDim.x + threadIdx.x; idx < total;
         idx += gridDim.x * blockDim.x) {
        int c = idx & cmask;
        float xn = (src[idx] - mu[c]) * inv[c];
        xn = fminf(3.f, fmaxf(-3.f, xn));
        float t = __expf(fmaf(-2.f * xn, xn, -8.f * xn));
        float r = __expf(xn * (16.f / 15.f));
        dst[idx] = make_float2(t, r);
    }
}

__global__ void k_final(const float2* __restrict__ tr, const float* __restrict__ cp3,
                        const float* __restrict__ x, const float* __restrict__ sw,
                        const float* __restrict__ sb, float* __restrict__ out) {
    int warp = threadIdx.x >> 5, lane = threadIdx.x & 31;
    int b = blockIdx.x * 8 + warp;
    float acc = 0.f;
    for (int i = lane; i < HD; i += 32) {
        float2 v = tr[(size_t)b * HD + i];
        const float* c = &cp3[i * NB];
        float p = c[0];
#pragma unroll
        for (int j = 1; j < NB; j++) p = fmaf(p, v.y, c[j]);
        acc = fmaf(v.x, p, acc);
    }
    for (int cidx = lane; cidx < IN1; cidx += 32)
        acc = fmaf(x[(size_t)b * IN1 + cidx], sw[cidx], acc);
#pragma unroll
    for (int off = 16; off; off >>= 1) acc += __shfl_xor_sync(0xffffffffu, acc, off);
    if (lane == 0) out[b] = acc + sb[0];
}

// ---------------- launch ---------------------------------------------------------
extern "C" void kernel_launch(void* const* d_in, const int* in_sizes, int n_in,
                              void* d_out, int out_size) {
    const float* x  = (const float*)d_in[0];
    const float* c1 = (const float*)d_in[1];
    const float* c2 = (const float*)d_in[2];
    const float* c3 = (const float*)d_in[3];
    const float* sw = (const float*)d_in[4];
    const float* sb = (const float*)d_in[5];
    float* out = (float*)d_out;

    __nv_bfloat16 *cb1h, *cb1l, *cb2h, *cb2l;
    float *h1, *h2, *cp3, *mu1, *inv1, *mu2, *inv2, *mu3, *inv3;
    float2* tr;
    cudaGetSymbolAddress((void**)&cb1h, g_cb1h);
    cudaGetSymbolAddress((void**)&cb1l, g_cb1l);
    cudaGetSymbolAddress((void**)&cb2h, g_cb2h);
    cudaGetSymbolAddress((void**)&cb2l, g_cb2l);
    cudaGetSymbolAddress((void**)&h1,   g_h1);
    cudaGetSymbolAddress((void**)&h2,   g_h2);
    cudaGetSymbolAddress((void**)&cp3,  g_cp3);
    cudaGetSymbolAddress((void**)&tr,   g_tr);
    cudaGetSymbolAddress((void**)&mu1,  g_mu1);
    cudaGetSymbolAddress((void**)&inv1, g_inv1);
    cudaGetSymbolAddress((void**)&mu2,  g_mu2);
    cudaGetSymbolAddress((void**)&inv2, g_inv2);
    cudaGetSymbolAddress((void**)&mu3,  g_mu3);
    cudaGetSymbolAddress((void**)&inv3, g_inv3);

    cudaFuncSetAttribute(k_gemm, cudaFuncAttributeMaxDynamicSharedMemorySize, GEMM_SMEM);

    // 0: stats(x) + c1 split + c3 transform ; 1: c2 split ; 2: stats_fin
    k_prep0a<<<NPART + HD + 1, 256>>>(x, c1, c3, cb1h, cb1l, cp3);
    k_csplit2<<<HD, 256>>>(c2, cb2h, cb2l);
    k_stats_fin<<<1, 256>>>(IN1, mu1, inv1);
    // 3: fused basis+GEMM layer 1 (ncu capture slot)
    k_gemm<<<dim3(HD / BN, B_ROWS / BM), 256, GEMM_SMEM>>>(x, mu1, inv1,
                                                           cb1h, cb1l, h1, K1, IN1);
    // layer 2
    k_stats_part<<<NPART, 256>>>(h1, HD);
    k_stats_fin<<<2, 256>>>(HD, mu2, inv2);
    k_gemm<<<dim3(HD / BN, B_ROWS / BM), 256, GEMM_SMEM>>>(h1, mu2, inv2,
                                                           cb2h, cb2l, h2, K2, HD);
    // layer 3 + skip
    k_stats_part<<<NPART, 256>>>(h2, HD);
    k_stats_fin<<<2, 256>>>(HD, mu3, inv3);
    k_prep_tr<<<4096, 256>>>(h2, mu3, inv3, HD - 1, B_ROWS * HD, tr);
    k_final<<<B_ROWS / 8, 256>>>(tr, cp3, x, sw, sb, out);
}

// round 10
// speedup vs baseline: 1.1029x; 1.0101x over previous
#include <cuda_runtime.h>
#include <cuda_bf16.h>
#include <math.h>
#include <stdint.h>

#define B_ROWS 16384
#define IN1    256
#define HD     512
#define NB     16
#define NPART  1024
#define K1     (IN1 * NB)   // 4096
#define K2     (HD * NB)    // 8192

// GEMM: CTA 128x128, 8 warps (2x4), warp tile 64x32, BK=64
// SMEM: A double-buffer (gen'd in-kernel) + 3-stage B ring + 3-slot src ring
#define BM 128
#define BN 128
#define BK 64
#define AB_BYTES   32768                    // per A buffer: hi 16K + lo 16K
#define AB_LO      16384
#define B_BASE     65536                    // after 2 A buffers
#define B_STAGE    32768                    // hi 16K + lo 16K
#define B_LO       16384
#define SRC_BASE   (B_BASE + 3 * B_STAGE)   // 163840
#define SRC_SLOT   2048
#define GEMM_SMEM  (SRC_BASE + 3 * SRC_SLOT)  // 169984

// ---------------- scratch (device globals) -----------------------------------
__device__ float g_mu1[IN1], g_inv1[IN1];
__device__ float g_mu2[HD],  g_inv2[HD];
__device__ float g_mu3[HD],  g_inv3[HD];
__device__ float g_ps[NPART * HD];
__device__ float g_pq[NPART * HD];
__device__ __align__(128) __nv_bfloat16 g_cb1h[(size_t)HD * K1];
__device__ __align__(128) __nv_bfloat16 g_cb1l[(size_t)HD * K1];
__device__ __align__(128) __nv_bfloat16 g_cb2h[(size_t)HD * K2];
__device__ __align__(128) __nv_bfloat16 g_cb2l[(size_t)HD * K2];
__device__ float  g_h1[(size_t)B_ROWS * HD];
__device__ float  g_h2[(size_t)B_ROWS * HD];
__device__ float  g_cp3[HD * NB];

// ---------------- PTX helpers --------------------------------------------------
__device__ __forceinline__ uint32_t smem_u32(const void* p) {
    uint32_t a;
    asm("{ .reg .u64 t; cvta.to.shared.u64 t, %1; cvt.u32.u64 %0, t; }" : "=r"(a) : "l"(p));
    return a;
}
__device__ __forceinline__ uint32_t sw128(uint32_t b) { return b ^ ((b >> 3) & 0x70u); }
__device__ __forceinline__ void cp16(uint32_t s, const void* g) {
    asm volatile("cp.async.cg.shared.global [%0], [%1], 16;" :: "r"(s), "l"(g));
}
#define CP_COMMIT() asm volatile("cp.async.commit_group;" ::: "memory")

__device__ __forceinline__ void ldmx4(uint32_t* r, uint32_t addr) {
    asm volatile("ldmatrix.sync.aligned.m8n8.x4.shared.b16 {%0,%1,%2,%3}, [%4];"
        : "=r"(r[0]), "=r"(r[1]), "=r"(r[2]), "=r"(r[3]) : "r"(addr));
}
// NOTE: non-volatile — pure register computation, lets ptxas interleave
// independent accumulator chains.
__device__ __forceinline__ void mma16816(float* c, const uint32_t* a, const uint32_t* b) {
    asm("mma.sync.aligned.m16n8k16.row.col.f32.bf16.bf16.f32 "
        "{%0,%1,%2,%3}, {%4,%5,%6,%7}, {%8,%9}, {%0,%1,%2,%3};"
        : "+f"(c[0]), "+f"(c[1]), "+f"(c[2]), "+f"(c[3])
        : "r"(a[0]), "r"(a[1]), "r"(a[2]), "r"(a[3]), "r"(b[0]), "r"(b[1]));
}
// packs (lo, hi) floats into bf16x2 word, lo at low half (RN)
__device__ __forceinline__ uint32_t bf16pack(float lo, float hi) {
    uint32_t w;
    asm("cvt.rn.bf16x2.f32 %0, %1, %2;" : "=r"(w) : "f"(hi), "f"(lo));
    return w;
}

// ---------------- stats core ----------------------------------------------------
__device__ __forceinline__ void stats_part_body(const float* __restrict__ src, int C,
                                                int bid, int tid) {
    const int rows = B_ROWS / NPART;   // 16
    const int r0 = bid * rows;
    float s[2] = {0.f, 0.f}, q[2] = {0.f, 0.f};
    const int ncc = C >> 8;
    for (int rr = 0; rr < rows; rr++) {
        const float* row = src + (size_t)(r0 + rr) * C;
        for (int cc = 0; cc < ncc; cc++) {
            float v = row[tid + (cc << 8)];
            s[cc] += v;
            q[cc] = fmaf(v, v, q[cc]);
        }
    }
    for (int cc = 0; cc < ncc; cc++) {
        g_ps[bid * C + tid + (cc << 8)] = s[cc];
        g_pq[bid * C + tid + (cc << 8)] = q[cc];
    }
}

__global__ void k_stats_part(const float* __restrict__ src, int C) {
    stats_part_body(src, C, blockIdx.x, threadIdx.x);
}

__global__ void k_stats_fin(int C, float* __restrict__ mu, float* __restrict__ inv) {
    int c = blockIdx.x * blockDim.x + threadIdx.x;
    if (c >= C) return;
    float s = 0.f, q = 0.f;
    for (int k = 0; k < NPART; k++) { s += g_ps[k * C + c]; q += g_pq[k * C + c]; }
    float m = s / (float)B_ROWS;
    float var = (q - s * m) / (float)(B_ROWS - 1);
    float sd = sqrtf(fmaxf(var, 0.f));
    mu[c] = m;
    inv[c] = 1.f / (sd + 1e-6f);
}

// ---------------- coeff split core ----------------------------------------------
__device__ __forceinline__ void coeff_split_body(const float* __restrict__ src, int K,
        __nv_bfloat16* __restrict__ Bh, __nv_bfloat16* __restrict__ Bl, int o, int tid) {
    for (int k = tid; k < K; k += 256) {
        int n = k & 15;
        float cn = fmaf((float)n, 4.f / 15.f, -2.f);
        float Kn = expf(-2.f * cn * cn);
        float v = src[(size_t)o * K + k] * Kn;
        __nv_bfloat16 h = __float2bfloat16(v);
        float lo = v - __bfloat162float(h);
        Bh[(size_t)o * K + k] = h;
        Bl[(size_t)o * K + k] = __float2bfloat16(lo);
    }
}

// fused: stats_part(x) + coeff_split(c1) + coeffs3
__global__ void k_prep0a(const float* __restrict__ x, const float* __restrict__ c1,
                         const float* __restrict__ c3,
                         __nv_bfloat16* __restrict__ cb1h, __nv_bfloat16* __restrict__ cb1l,
                         float* __restrict__ cp3) {
    int bid = blockIdx.x, tid = threadIdx.x;
    if (bid < NPART) {
        stats_part_body(x, IN1, bid, tid);
    } else if (bid < NPART + HD) {
        coeff_split_body(c1, K1, cb1h, cb1l, bid - NPART, tid);
    } else {
        for (int w = tid; w < HD * NB; w += 256) {
            int i = w >> 4, j = w & 15;
            int n = 15 - j;
            float cn = fmaf((float)n, 4.f / 15.f, -2.f);
            float Kn = expf(-2.f * cn * cn);
            cp3[i * NB + j] = c3[(size_t)i * NB + n] * Kn;
        }
    }
}

__global__ void k_csplit2(const float* __restrict__ c2,
                          __nv_bfloat16* __restrict__ cb2h, __nv_bfloat16* __restrict__ cb2l) {
    coeff_split_body(c2, K2, cb2h, cb2l, blockIdx.x, threadIdx.x);
}

// ---------------- fused basis-gen + split-bf16 GEMM + tanh ----------------------
__device__ __forceinline__ void load_B(uint32_t stage_base,
        const __nv_bfloat16* __restrict__ Bh, const __nv_bfloat16* __restrict__ Bl,
        int on0, int k0, int K, int tid) {
#pragma unroll
    for (int q = 0; q < 4; q++) {          // 128 rows x 8 16B-chunks, 256 threads
        int e = tid + (q << 8);
        int row = e >> 3, ch = e & 7;
        uint32_t so = sw128((uint32_t)(row << 7) + (ch << 4));
        size_t gb = (size_t)(on0 + row) * K + k0 + (ch << 3);
        cp16(stage_base + so, Bh + gb);
        cp16(stage_base + B_LO + so, Bl + gb);
    }
}

// expand one (row, icol) pair of the NEXT chunk into swizzled A-tile (hi/lo bf16)
__device__ __forceinline__ void gen_pair(char* smem, int p, uint32_t src_slot,
        uint32_t abuf, int i0, const float* __restrict__ mu,
        const float* __restrict__ inv) {
    int row = p >> 2, icol = p & 3;
    float v = reinterpret_cast<const float*>(smem + SRC_BASE + src_slot * SRC_SLOT)
                  [(row << 2) + icol];
    int i = i0 + icol;
    float xn = (v - __ldg(mu + i)) * __ldg(inv + i);
    xn = fminf(3.f, fmaxf(-3.f, xn));
    float t = __expf(fmaf(-2.f * xn, xn, -8.f * xn));
    float r = __expf(xn * (16.f / 15.f));
    uint32_t wh[8], wl[8];
    float pv = t;
#pragma unroll
    for (int m = 0; m < 8; m++) {
        float p0 = pv;
        float p1 = pv * r;
        pv = p1 * r;
        uint32_t w = bf16pack(p0, p1);
        wh[m] = w;
        float h0 = __uint_as_float(w << 16);
        float h1 = __uint_as_float(w & 0xffff0000u);
        wl[m] = bf16pack(p0 - h0, p1 - h1);
    }
    uint32_t base = (uint32_t)(row << 7) + (icol << 5);
    uint32_t a0 = sw128(base), a1 = sw128(base + 16);
    *reinterpret_cast<uint4*>(smem + abuf + a0) = make_uint4(wh[0], wh[1], wh[2], wh[3]);
    *reinterpret_cast<uint4*>(smem + abuf + a1) = make_uint4(wh[4], wh[5], wh[6], wh[7]);
    *reinterpret_cast<uint4*>(smem + abuf + AB_LO + a0) = make_uint4(wl[0], wl[1], wl[2], wl[3]);
    *reinterpret_cast<uint4*>(smem + abuf + AB_LO + a1) = make_uint4(wl[4], wl[5], wl[6], wl[7]);
}

__global__ void __launch_bounds__(256, 1)
k_gemm(const float* __restrict__ src, const float* __restrict__ mu,
       const float* __restrict__ inv,
       const __nv_bfloat16* __restrict__ Bh, const __nv_bfloat16* __restrict__ Bl,
       float* __restrict__ out, int K, int C) {
    extern __shared__ __align__(1024) char smem_raw[];
    const uint32_t base = smem_u32(smem_raw);
    const int tid = threadIdx.x;
    const int lane = tid & 31, wid = tid >> 5;
    const int wr = wid & 1, wc = wid >> 1;     // 2x4 warp grid: 64x32 per warp
    const int bm0 = blockIdx.y << 7, on0 = blockIdx.x << 7;
    const int NCH = K >> 6;

    float acc[4][4][4];
#pragma unroll
    for (int mt = 0; mt < 4; mt++)
#pragma unroll
        for (int nt = 0; nt < 4; nt++)
#pragma unroll
            for (int e = 0; e < 4; e++) acc[mt][nt][e] = 0.f;

    // prologue: commit B+src for chunks 0,1 (one group each)
    load_B(base + B_BASE, Bh, Bl, on0, 0, K, tid);
    if (tid < 128) cp16(base + SRC_BASE + (tid << 4),
                        src + (size_t)(bm0 + tid) * C);
    CP_COMMIT();
    load_B(base + B_BASE + B_STAGE, Bh, Bl, on0, BK, K, tid);
    if (tid < 128) cp16(base + SRC_BASE + SRC_SLOT + (tid << 4),
                        src + (size_t)(bm0 + tid) * C + 4);
    CP_COMMIT();
    asm volatile("cp.async.wait_group 1;" ::: "memory");   // group 0 done
    __syncthreads();
    // gen chunk 0 into A buffer 0
    gen_pair(smem_raw, tid * 2,     0, 0, 0, mu, inv);
    gen_pair(smem_raw, tid * 2 + 1, 0, 0, 0, mu, inv);

    const int g = lane >> 3, lr = lane & 7;

    for (int c = 0; c < NCH; c++) {
        asm volatile("cp.async.wait_group 0;" ::: "memory");  // groups <= c+1 done
        __syncthreads();   // visibility of cp(src c+1, B c+1) + gen(c) + frees stage (c+2)%3

        if (c + 2 < NCH) {
            int s = (c + 2) % 3;
            load_B(base + B_BASE + (uint32_t)s * B_STAGE, Bh, Bl, on0, (c + 2) << 6, K, tid);
            if (tid < 128) cp16(base + SRC_BASE + (uint32_t)s * SRC_SLOT + (tid << 4),
                                src + (size_t)(bm0 + tid) * C + ((c + 2) << 2));
            CP_COMMIT();
        }

        const uint32_t abuf = (uint32_t)(c & 1) * AB_BYTES;
        const uint32_t bst  = B_BASE + (uint32_t)(c % 3) * B_STAGE;
        const bool do_gen = (c + 1 < NCH);
        const uint32_t gslot = (uint32_t)((c + 1) % 3);
        const uint32_t gbuf = (uint32_t)((c + 1) & 1) * AB_BYTES;
        const int gi0 = (c + 1) << 2;

#pragma unroll
        for (int kk = 0; kk < 4; kk++) {
            uint32_t afh[4][4], afl[4][4];
#pragma unroll
            for (int mt = 0; mt < 4; mt++) {
                int m_local = wr * 64 + mt * 16 + (g & 1) * 8 + lr;
                uint32_t off = sw128((uint32_t)(m_local << 7) + (kk << 5) + ((g >> 1) << 4));
                ldmx4(afh[mt], base + abuf + off);
                ldmx4(afl[mt], base + abuf + AB_LO + off);
            }
            uint32_t bfh[2][4], bfl[2][4];
#pragma unroll
            for (int n2 = 0; n2 < 2; n2++) {
                int n_local = wc * 32 + n2 * 16 + (g >> 1) * 8 + lr;
                uint32_t off = sw128((uint32_t)(n_local << 7) + (kk << 5) + ((g & 1) << 4));
                ldmx4(bfh[n2], base + bst + off);
                ldmx4(bfl[n2], base + bst + B_LO + off);
            }
            // term-major issue: 16 independent MMAs between successive writes
            // to the same accumulator (per-acc order preserved: B0, B1, B2)
#pragma unroll
            for (int term = 0; term < 3; term++)
#pragma unroll
                for (int mt = 0; mt < 4; mt++)
#pragma unroll
                    for (int nt = 0; nt < 4; nt++) {
                        const uint32_t* A = (term == 2) ? afl[mt] : afh[mt];
                        const uint32_t* B = (term == 1)
                            ? &bfl[nt >> 1][(nt & 1) * 2]
                            : &bfh[nt >> 1][(nt & 1) * 2];
                        mma16816(acc[mt][nt], A, B);
                    }
            if (kk == 1 && do_gen) gen_pair(smem_raw, tid * 2,     gslot, gbuf, gi0, mu, inv);
            if (kk == 3 && do_gen) gen_pair(smem_raw, tid * 2 + 1, gslot, gbuf, gi0, mu, inv);
        }
    }

    // epilogue: tanh + store
#pragma unroll
    for (int mt = 0; mt < 4; mt++) {
        int row0 = bm0 + wr * 64 + mt * 16 + (lane >> 2);
#pragma unroll
        for (int nt = 0; nt < 4; nt++) {
            int col = on0 + wc * 32 + nt * 8 + (lane & 3) * 2;
            float2 v0, v1;
            v0.x = tanhf(acc[mt][nt][0]);
            v0.y = tanhf(acc[mt][nt][1]);
            v1.x = tanhf(acc[mt][nt][2]);
            v1.y = tanhf(acc[mt][nt][3]);
            *reinterpret_cast<float2*>(out + (size_t)row0 * HD + col) = v0;
            *reinterpret_cast<float2*>(out + (size_t)(row0 + 8) * HD + col) = v1;
        }
    }
}

// ---------------- final layer: t,r computed inline + Horner + skip ---------------
__global__ void k_final(const float* __restrict__ h2, const float* __restrict__ mu,
                        const float* __restrict__ inv, const float* __restrict__ cp3,
                        const float* __restrict__ x, const float* __restrict__ sw,
                        const float* __restrict__ sb, float* __restrict__ out) {
    int warp = threadIdx.x >> 5, lane = threadIdx.x & 31;
    int b = blockIdx.x * 8 + warp;
    float acc = 0.f;
    for (int i = lane; i < HD; i += 32) {
        float xn = (h2[(size_t)b * HD + i] - mu[i]) * inv[i];
        xn = fminf(3.f, fmaxf(-3.f, xn));
        float t = __expf(fmaf(-2.f * xn, xn, -8.f * xn));
        float r = __expf(xn * (16.f / 15.f));
        const float* c = &cp3[i * NB];
        float p = c[0];
#pragma unroll
        for (int j = 1; j < NB; j++) p = fmaf(p, r, c[j]);
        acc = fmaf(t, p, acc);
    }
    for (int cidx = lane; cidx < IN1; cidx += 32)
        acc = fmaf(x[(size_t)b * IN1 + cidx], sw[cidx], acc);
#pragma unroll
    for (int off = 16; off; off >>= 1) acc += __shfl_xor_sync(0xffffffffu, acc, off);
    if (lane == 0) out[b] = acc + sb[0];
}

// ---------------- launch ---------------------------------------------------------
extern "C" void kernel_launch(void* const* d_in, const int* in_sizes, int n_in,
                              void* d_out, int out_size) {
    const float* x  = (const float*)d_in[0];
    const float* c1 = (const float*)d_in[1];
    const float* c2 = (const float*)d_in[2];
    const float* c3 = (const float*)d_in[3];
    const float* sw = (const float*)d_in[4];
    const float* sb = (const float*)d_in[5];
    float* out = (float*)d_out;

    __nv_bfloat16 *cb1h, *cb1l, *cb2h, *cb2l;
    float *h1, *h2, *cp3, *mu1, *inv1, *mu2, *inv2, *mu3, *inv3;
    cudaGetSymbolAddress((void**)&cb1h, g_cb1h);
    cudaGetSymbolAddress((void**)&cb1l, g_cb1l);
    cudaGetSymbolAddress((void**)&cb2h, g_cb2h);
    cudaGetSymbolAddress((void**)&cb2l, g_cb2l);
    cudaGetSymbolAddress((void**)&h1,   g_h1);
    cudaGetSymbolAddress((void**)&h2,   g_h2);
    cudaGetSymbolAddress((void**)&cp3,  g_cp3);
    cudaGetSymbolAddress((void**)&mu1,  g_mu1);
    cudaGetSymbolAddress((void**)&inv1, g_inv1);
    cudaGetSymbolAddress((void**)&mu2,  g_mu2);
    cudaGetSymbolAddress((void**)&inv2, g_inv2);
    cudaGetSymbolAddress((void**)&mu3,  g_mu3);
    cudaGetSymbolAddress((void**)&inv3, g_inv3);

    cudaFuncSetAttribute(k_gemm, cudaFuncAttributeMaxDynamicSharedMemorySize, GEMM_SMEM);

    // 0: stats(x) + c1 split + c3 transform ; 1: c2 split ; 2: stats_fin
    k_prep0a<<<NPART + HD + 1, 256>>>(x, c1, c3, cb1h, cb1l, cp3);
    k_csplit2<<<HD, 256>>>(c2, cb2h, cb2l);
    k_stats_fin<<<1, 256>>>(IN1, mu1, inv1);
    // 3: fused basis+GEMM layer 1 (ncu capture slot)
    k_gemm<<<dim3(HD / BN, B_ROWS / BM), 256, GEMM_SMEM>>>(x, mu1, inv1,
                                                           cb1h, cb1l, h1, K1, IN1);
    // layer 2
    k_stats_part<<<NPART, 256>>>(h1, HD);
    k_stats_fin<<<2, 256>>>(HD, mu2, inv2);
    k_gemm<<<dim3(HD / BN, B_ROWS / BM), 256, GEMM_SMEM>>>(h1, mu2, inv2,
                                                           cb2h, cb2l, h2, K2, HD);
    // layer 3 + skip (t,r inline)
    k_stats_part<<<NPART, 256>>>(h2, HD);
    k_stats_fin<<<2, 256>>>(HD, mu3, inv3);
    k_final<<<B_ROWS / 8, 256>>>(h2, mu3, inv3, cp3, x, sw, sb, out);
}

// round 13
// speedup vs baseline: 1.1581x; 1.0500x over previous
#include <cuda_runtime.h>
#include <cuda_bf16.h>
#include <math.h>
#include <stdint.h>

#define B_ROWS 16384
#define IN1    256
#define HD     512
#define NB     16
#define NPARTX 1024          // partials for x stats
#define NPARTH 128           // partials for h stats (= GEMM grid.y)
#define K1     (IN1 * NB)    // 4096
#define K2     (HD * NB)     // 8192

// GEMM: CTA 128x128, 8 warps (2x4), warp tile 64x32, BK=64
#define BM 128
#define BN 128
#define BK 64
#define AB_BYTES   32768
#define AB_LO      16384
#define B_BASE     65536
#define B_STAGE    32768
#define B_LO       16384
#define SRC_BASE   (B_BASE + 3 * B_STAGE)    // 163840
#define SRC_SLOT   2048
#define STAT_BASE  (SRC_BASE + 3 * SRC_SLOT) // 169984  (2x128 floats s + q)
#define GEMM_SMEM  (STAT_BASE + 4096)        // 174080

// ---------------- scratch (device globals) -----------------------------------
__device__ float g_mu1[IN1], g_inv1[IN1];
__device__ float g_mu2[HD],  g_inv2[HD];
__device__ float g_mu3[HD],  g_inv3[HD];
__device__ float g_ps[NPARTX * HD];
__device__ float g_pq[NPARTX * HD];
__device__ __align__(128) __nv_bfloat16 g_cb1h[(size_t)HD * K1];
__device__ __align__(128) __nv_bfloat16 g_cb1l[(size_t)HD * K1];
__device__ __align__(128) __nv_bfloat16 g_cb2h[(size_t)HD * K2];
__device__ __align__(128) __nv_bfloat16 g_cb2l[(size_t)HD * K2];
__device__ float  g_h1[(size_t)B_ROWS * HD];
__device__ float  g_h2[(size_t)B_ROWS * HD];
__device__ float  g_cp3[HD * NB];

// ---------------- PTX helpers --------------------------------------------------
__device__ __forceinline__ uint32_t smem_u32(const void* p) {
    uint32_t a;
    asm("{ .reg .u64 t; cvta.to.shared.u64 t, %1; cvt.u32.u64 %0, t; }" : "=r"(a) : "l"(p));
    return a;
}
__device__ __forceinline__ uint32_t sw128(uint32_t b) { return b ^ ((b >> 3) & 0x70u); }
__device__ __forceinline__ void cp16(uint32_t s, const void* g) {
    asm volatile("cp.async.cg.shared.global [%0], [%1], 16;" :: "r"(s), "l"(g));
}
#define CP_COMMIT() asm volatile("cp.async.commit_group;" ::: "memory")

__device__ __forceinline__ void ldmx4(uint32_t* r, uint32_t addr) {
    asm volatile("ldmatrix.sync.aligned.m8n8.x4.shared.b16 {%0,%1,%2,%3}, [%4];"
        : "=r"(r[0]), "=r"(r[1]), "=r"(r[2]), "=r"(r[3]) : "r"(addr));
}
// bf16 operands, fp32 accumulate — PROVEN precision path (R9: rel_err 1.0e-4)
__device__ __forceinline__ void mma_f32(float* c, const uint32_t* a, const uint32_t* b) {
    asm("mma.sync.aligned.m16n8k16.row.col.f32.bf16.bf16.f32 "
        "{%0,%1,%2,%3}, {%4,%5,%6,%7}, {%8,%9}, {%0,%1,%2,%3};"
        : "+f"(c[0]), "+f"(c[1]), "+f"(c[2]), "+f"(c[3])
        : "r"(a[0]), "r"(a[1]), "r"(a[2]), "r"(a[3]), "r"(b[0]), "r"(b[1]));
}
// packs (lo, hi) floats into bf16x2 word, lo at low half (RN)
__device__ __forceinline__ uint32_t bf16pack(float lo, float hi) {
    uint32_t w;
    asm("cvt.rn.bf16x2.f32 %0, %1, %2;" : "=r"(w) : "f"(hi), "f"(lo));
    return w;
}

// ---------------- stats core ----------------------------------------------------
__device__ __forceinline__ void stats_part_body(const float* __restrict__ src, int C,
                                                int bid, int tid) {
    const int rows = B_ROWS / NPARTX;   // 16
    const int r0 = bid * rows;
    float s = 0.f, q = 0.f;
    for (int rr = 0; rr < rows; rr++) {
        float v = src[(size_t)(r0 + rr) * C + tid];
        s += v;
        q = fmaf(v, v, q);
    }
    g_ps[bid * C + tid] = s;
    g_pq[bid * C + tid] = q;
}

__global__ void k_stats_fin(int C, int P, float* __restrict__ mu, float* __restrict__ inv) {
    int c = blockIdx.x * blockDim.x + threadIdx.x;
    if (c >= C) return;
    float s = 0.f, q = 0.f;
    for (int k = 0; k < P; k++) { s += g_ps[k * C + c]; q += g_pq[k * C + c]; }
    float m = s / (float)B_ROWS;
    float var = (q - s * m) / (float)(B_ROWS - 1);
    float sd = sqrtf(fmaxf(var, 0.f));
    mu[c] = m;
    inv[c] = 1.f / (sd + 1e-6f);
}

// ---------------- coeff split (bf16 hi/lo, Kn folded) ----------------------------
__device__ __forceinline__ void coeff_split_body(const float* __restrict__ src, int K,
        __nv_bfloat16* __restrict__ Bh, __nv_bfloat16* __restrict__ Bl, int o, int tid) {
    for (int k = tid; k < K; k += 256) {
        int n = k & 15;
        float cn = fmaf((float)n, 4.f / 15.f, -2.f);
        float Kn = expf(-2.f * cn * cn);
        float v = src[(size_t)o * K + k] * Kn;
        __nv_bfloat16 h = __float2bfloat16(v);
        Bh[(size_t)o * K + k] = h;
        Bl[(size_t)o * K + k] = __float2bfloat16(v - __bfloat162float(h));
    }
}

// fused: stats_part(x) + coeff_split(c1) + coeffs3
__global__ void k_prep0a(const float* __restrict__ x, const float* __restrict__ c1,
                         const float* __restrict__ c3,
                         __nv_bfloat16* __restrict__ cb1h, __nv_bfloat16* __restrict__ cb1l,
                         float* __restrict__ cp3) {
    int bid = blockIdx.x, tid = threadIdx.x;
    if (bid < NPARTX) {
        stats_part_body(x, IN1, bid, tid);
    } else if (bid < NPARTX + HD) {
        coeff_split_body(c1, K1, cb1h, cb1l, bid - NPARTX, tid);
    } else {
        for (int w = tid; w < HD * NB; w += 256) {
            int i = w >> 4, j = w & 15;
            int n = 15 - j;
            float cn = fmaf((float)n, 4.f / 15.f, -2.f);
            float Kn = expf(-2.f * cn * cn);
            cp3[i * NB + j] = c3[(size_t)i * NB + n] * Kn;
        }
    }
}

__global__ void k_csplit2(const float* __restrict__ c2,
                          __nv_bfloat16* __restrict__ cb2h, __nv_bfloat16* __restrict__ cb2l) {
    coeff_split_body(c2, K2, cb2h, cb2l, blockIdx.x, threadIdx.x);
}

// ---------------- fused basis-gen + split-bf16 GEMM + tanh + stats ---------------
__device__ __forceinline__ void load_B(uint32_t stage_base,
        const __nv_bfloat16* __restrict__ Bh, const __nv_bfloat16* __restrict__ Bl,
        int on0, int k0, int K, int tid) {
#pragma unroll
    for (int q = 0; q < 4; q++) {
        int e = tid + (q << 8);
        int row = e >> 3, ch = e & 7;
        uint32_t so = sw128((uint32_t)(row << 7) + (ch << 4));
        size_t gb = (size_t)(on0 + row) * K + k0 + (ch << 3);
        cp16(stage_base + so, Bh + gb);
        cp16(stage_base + B_LO + so, Bl + gb);
    }
}

__device__ __forceinline__ void gen_pair(char* smem, int p, uint32_t src_slot,
        uint32_t abuf, int i0, const float* __restrict__ mu,
        const float* __restrict__ inv) {
    int row = p >> 2, icol = p & 3;
    float v = reinterpret_cast<const float*>(smem + SRC_BASE + src_slot * SRC_SLOT)
                  [(row << 2) + icol];
    int i = i0 + icol;
    float xn = (v - __ldg(mu + i)) * __ldg(inv + i);
    xn = fminf(3.f, fmaxf(-3.f, xn));
    float t = __expf(fmaf(-2.f * xn, xn, -8.f * xn));
    float r = __expf(xn * (16.f / 15.f));
    uint32_t wh[8], wl[8];
    float pv = t;
#pragma unroll
    for (int m = 0; m < 8; m++) {
        float p0 = pv;
        float p1 = pv * r;
        pv = p1 * r;
        uint32_t w = bf16pack(p0, p1);
        wh[m] = w;
        float h0 = __uint_as_float(w << 16);
        float h1 = __uint_as_float(w & 0xffff0000u);
        wl[m] = bf16pack(p0 - h0, p1 - h1);
    }
    uint32_t base = (uint32_t)(row << 7) + (icol << 5);
    uint32_t a0 = sw128(base), a1 = sw128(base + 16);
    *reinterpret_cast<uint4*>(smem + abuf + a0) = make_uint4(wh[0], wh[1], wh[2], wh[3]);
    *reinterpret_cast<uint4*>(smem + abuf + a1) = make_uint4(wh[4], wh[5], wh[6], wh[7]);
    *reinterpret_cast<uint4*>(smem + abuf + AB_LO + a0) = make_uint4(wl[0], wl[1], wl[2], wl[3]);
    *reinterpret_cast<uint4*>(smem + abuf + AB_LO + a1) = make_uint4(wl[4], wl[5], wl[6], wl[7]);
}

__global__ void __launch_bounds__(256, 1)
k_gemm(const float* __restrict__ src, const float* __restrict__ mu,
       const float* __restrict__ inv,
       const __nv_bfloat16* __restrict__ Bh, const __nv_bfloat16* __restrict__ Bl,
       float* __restrict__ out, int K, int C) {
    extern __shared__ __align__(1024) char smem_raw[];
    const uint32_t base = smem_u32(smem_raw);
    const int tid = threadIdx.x;
    const int lane = tid & 31, wid = tid >> 5;
    const int wr = wid & 1, wc = wid >> 1;
    const int bm0 = blockIdx.y << 7, on0 = blockIdx.x << 7;
    const int NCH = K >> 6;

    float acc[4][4][4];
#pragma unroll
    for (int mt = 0; mt < 4; mt++)
#pragma unroll
        for (int nt = 0; nt < 4; nt++)
#pragma unroll
            for (int e = 0; e < 4; e++) acc[mt][nt][e] = 0.f;

    load_B(base + B_BASE, Bh, Bl, on0, 0, K, tid);
    if (tid < 128) cp16(base + SRC_BASE + (tid << 4),
                        src + (size_t)(bm0 + tid) * C);
    CP_COMMIT();
    load_B(base + B_BASE + B_STAGE, Bh, Bl, on0, BK, K, tid);
    if (tid < 128) cp16(base + SRC_BASE + SRC_SLOT + (tid << 4),
                        src + (size_t)(bm0 + tid) * C + 4);
    CP_COMMIT();
    asm volatile("cp.async.wait_group 1;" ::: "memory");
    __syncthreads();
    gen_pair(smem_raw, tid * 2,     0, 0, 0, mu, inv);
    gen_pair(smem_raw, tid * 2 + 1, 0, 0, 0, mu, inv);

    const int g = lane >> 3, lr = lane & 7;

    for (int c = 0; c < NCH; c++) {
        asm volatile("cp.async.wait_group 0;" ::: "memory");
        __syncthreads();

        if (c + 2 < NCH) {
            int s = (c + 2) % 3;
            load_B(base + B_BASE + (uint32_t)s * B_STAGE, Bh, Bl, on0, (c + 2) << 6, K, tid);
            if (tid < 128) cp16(base + SRC_BASE + (uint32_t)s * SRC_SLOT + (tid << 4),
                                src + (size_t)(bm0 + tid) * C + ((c + 2) << 2));
            CP_COMMIT();
        }

        const uint32_t abuf = (uint32_t)(c & 1) * AB_BYTES;
        const uint32_t bst  = B_BASE + (uint32_t)(c % 3) * B_STAGE;
        const bool do_gen = (c + 1 < NCH);
        const uint32_t gslot = (uint32_t)((c + 1) % 3);
        const uint32_t gbuf = (uint32_t)((c + 1) & 1) * AB_BYTES;
        const int gi0 = (c + 1) << 2;

#pragma unroll
        for (int kk = 0; kk < 4; kk++) {
            uint32_t afh[4][4], afl[4][4];
#pragma unroll
            for (int mt = 0; mt < 4; mt++) {
                int m_local = wr * 64 + mt * 16 + (g & 1) * 8 + lr;
                uint32_t off = sw128((uint32_t)(m_local << 7) + (kk << 5) + ((g >> 1) << 4));
                ldmx4(afh[mt], base + abuf + off);
                ldmx4(afl[mt], base + abuf + AB_LO + off);
            }
            uint32_t bfh[2][4], bfl[2][4];
#pragma unroll
            for (int n2 = 0; n2 < 2; n2++) {
                int n_local = wc * 32 + n2 * 16 + (g >> 1) * 8 + lr;
                uint32_t off = sw128((uint32_t)(n_local << 7) + (kk << 5) + ((g & 1) << 4));
                ldmx4(bfh[n2], base + bst + off);
                ldmx4(bfl[n2], base + bst + B_LO + off);
            }
            // term-major: per-acc order preserved (hi*Bh, hi*Bl, lo*Bh), fp32 acc
#pragma unroll
            for (int term = 0; term < 3; term++)
#pragma unroll
                for (int mt = 0; mt < 4; mt++)
#pragma unroll
                    for (int nt = 0; nt < 4; nt++) {
                        const uint32_t* A = (term == 2) ? afl[mt] : afh[mt];
                        const uint32_t* B = (term == 1)
                            ? &bfl[nt >> 1][(nt & 1) * 2]
                            : &bfh[nt >> 1][(nt & 1) * 2];
                        mma_f32(acc[mt][nt], A, B);
                    }

            if (kk == 1 && do_gen) gen_pair(smem_raw, tid * 2,     gslot, gbuf, gi0, mu, inv);
            if (kk == 3 && do_gen) gen_pair(smem_raw, tid * 2 + 1, gslot, gbuf, gi0, mu, inv);
        }
    }

    // epilogue: tanh + store + column-stats partials
    float s_e[4][2], q_e[4][2];
#pragma unroll
    for (int nt = 0; nt < 4; nt++) { s_e[nt][0] = s_e[nt][1] = 0.f; q_e[nt][0] = q_e[nt][1] = 0.f; }

#pragma unroll
    for (int mt = 0; mt < 4; mt++) {
        int row0 = bm0 + wr * 64 + mt * 16 + (lane >> 2);
#pragma unroll
        for (int nt = 0; nt < 4; nt++) {
            int col = on0 + wc * 32 + nt * 8 + (lane & 3) * 2;
            float2 v0, v1;
            v0.x = tanhf(acc[mt][nt][0]);
            v0.y = tanhf(acc[mt][nt][1]);
            v1.x = tanhf(acc[mt][nt][2]);
            v1.y = tanhf(acc[mt][nt][3]);
            *reinterpret_cast<float2*>(out + (size_t)row0 * HD + col) = v0;
            *reinterpret_cast<float2*>(out + (size_t)(row0 + 8) * HD + col) = v1;
            s_e[nt][0] += v0.x + v1.x;  s_e[nt][1] += v0.y + v1.y;
            q_e[nt][0] += v0.x * v0.x + v1.x * v1.x;
            q_e[nt][1] += v0.y * v0.y + v1.y * v1.y;
        }
    }
    // reduce over the 8 lanes sharing the same (lane&3)
    float* s_buf = reinterpret_cast<float*>(smem_raw + STAT_BASE);          // [2][128]
    float* q_buf = reinterpret_cast<float*>(smem_raw + STAT_BASE + 1024);   // [2][128]
#pragma unroll
    for (int nt = 0; nt < 4; nt++)
#pragma unroll
        for (int j = 0; j < 2; j++) {
            float s = s_e[nt][j], q = q_e[nt][j];
#pragma unroll
            for (int off = 4; off < 32; off <<= 1) {
                s += __shfl_xor_sync(0xffffffffu, s, off);
                q += __shfl_xor_sync(0xffffffffu, q, off);
            }
            if (lane < 4) {
                int colL = wc * 32 + nt * 8 + lane * 2 + j;
                s_buf[wr * 128 + colL] = s;
                q_buf[wr * 128 + colL] = q;
            }
        }
    __syncthreads();
    if (tid < 128) {
        g_ps[blockIdx.y * HD + on0 + tid] = s_buf[tid] + s_buf[128 + tid];
        g_pq[blockIdx.y * HD + on0 + tid] = q_buf[tid] + q_buf[128 + tid];
    }
}

// ---------------- final layer: t,r inline + Horner + skip ------------------------
__global__ void k_final(const float* __restrict__ h2, const float* __restrict__ mu,
                        const float* __restrict__ inv, const float* __restrict__ cp3,
                        const float* __restrict__ x, const float* __restrict__ sw,
                        const float* __restrict__ sb, float* __restrict__ out) {
    int warp = threadIdx.x >> 5, lane = threadIdx.x & 31;
    int b = blockIdx.x * 8 + warp;
    float acc = 0.f;
    for (int i = lane; i < HD; i += 32) {
        float xn = (h2[(size_t)b * HD + i] - mu[i]) * inv[i];
        xn = fminf(3.f, fmaxf(-3.f, xn));
        float t = __expf(fmaf(-2.f * xn, xn, -8.f * xn));
        float r = __expf(xn * (16.f / 15.f));
        const float* c = &cp3[i * NB];
        float p = c[0];
#pragma unroll
        for (int j = 1; j < NB; j++) p = fmaf(p, r, c[j]);
        acc = fmaf(t, p, acc);
    }
    for (int cidx = lane; cidx < IN1; cidx += 32)
        acc = fmaf(x[(size_t)b * IN1 + cidx], sw[cidx], acc);
#pragma unroll
    for (int off = 16; off; off >>= 1) acc += __shfl_xor_sync(0xffffffffu, acc, off);
    if (lane == 0) out[b] = acc + sb[0];
}

// ---------------- launch ---------------------------------------------------------
extern "C" void kernel_launch(void* const* d_in, const int* in_sizes, int n_in,
                              void* d_out, int out_size) {
    const float* x  = (const float*)d_in[0];
    const float* c1 = (const float*)d_in[1];
    const float* c2 = (const float*)d_in[2];
    const float* c3 = (const float*)d_in[3];
    const float* sw = (const float*)d_in[4];
    const float* sb = (const float*)d_in[5];
    float* out = (float*)d_out;

    __nv_bfloat16 *cb1h, *cb1l, *cb2h, *cb2l;
    float *h1, *h2, *cp3, *mu1, *inv1, *mu2, *inv2, *mu3, *inv3;
    cudaGetSymbolAddress((void**)&cb1h, g_cb1h);
    cudaGetSymbolAddress((void**)&cb1l, g_cb1l);
    cudaGetSymbolAddress((void**)&cb2h, g_cb2h);
    cudaGetSymbolAddress((void**)&cb2l, g_cb2l);
    cudaGetSymbolAddress((void**)&h1,   g_h1);
    cudaGetSymbolAddress((void**)&h2,   g_h2);
    cudaGetSymbolAddress((void**)&cp3,  g_cp3);
    cudaGetSymbolAddress((void**)&mu1,  g_mu1);
    cudaGetSymbolAddress((void**)&inv1, g_inv1);
    cudaGetSymbolAddress((void**)&mu2,  g_mu2);
    cudaGetSymbolAddress((void**)&inv2, g_inv2);
    cudaGetSymbolAddress((void**)&mu3,  g_mu3);
    cudaGetSymbolAddress((void**)&inv3, g_inv3);

    cudaFuncSetAttribute(k_gemm, cudaFuncAttributeMaxDynamicSharedMemorySize, GEMM_SMEM);

    // 0: stats(x) + c1 split + c3 transform ; 1: c2 split ; 2: stats_fin(x)
    k_prep0a<<<NPARTX + HD + 1, 256>>>(x, c1, c3, cb1h, cb1l, cp3);
    k_csplit2<<<HD, 256>>>(c2, cb2h, cb2l);
    k_stats_fin<<<1, 256>>>(IN1, NPARTX, mu1, inv1);
    // 3: fused basis+GEMM layer 1 (writes h1 + its column-stat partials)
    k_gemm<<<dim3(HD / BN, B_ROWS / BM), 256, GEMM_SMEM>>>(x, mu1, inv1,
                                                           cb1h, cb1l, h1, K1, IN1);
    k_stats_fin<<<2, 256>>>(HD, NPARTH, mu2, inv2);
    // layer 2 (writes h2 + partials)
    k_gemm<<<dim3(HD / BN, B_ROWS / BM), 256, GEMM_SMEM>>>(h1, mu2, inv2,
                                                           cb2h, cb2l, h2, K2, HD);
    k_stats_fin<<<2, 256>>>(HD, NPARTH, mu3, inv3);
    // layer 3 + skip
    k_final<<<B_ROWS / 8, 256>>>(h2, mu3, inv3, cp3, x, sw, sb, out);
}

// round 14
// speedup vs baseline: 1.1938x; 1.0309x over previous
#include <cuda_runtime.h>
#include <cuda_bf16.h>
#include <math.h>
#include <stdint.h>

#define B_ROWS 16384
#define IN1    256
#define HD     512
#define NB     16
#define NPARTX 1024          // partials for x stats
#define NPARTH 128           // partials for h stats (= GEMM grid.y)
#define K1     (IN1 * NB)    // 4096
#define K2     (HD * NB)     // 8192

// GEMM: CTA 128x128, 8 warps (2x4), warp tile 64x32, BK=64
#define BM 128
#define BN 128
#define BK 64
#define AB_BYTES   32768
#define AB_LO      16384
#define B_BASE     65536
#define B_STAGE    32768
#define B_LO       16384
#define SRC_BASE   (B_BASE + 3 * B_STAGE)    // 163840
#define SRC_SLOT   2048
#define STAT_BASE  (SRC_BASE + 3 * SRC_SLOT) // 169984  (2x128 floats s + q)
#define GEMM_SMEM  (STAT_BASE + 4096)        // 174080

// ---------------- scratch (device globals) -----------------------------------
__device__ float g_mu1[IN1], g_inv1[IN1];
__device__ float g_mu2[HD],  g_inv2[HD];
__device__ float g_mu3[HD],  g_inv3[HD];
__device__ float g_ps[NPARTX * HD];
__device__ float g_pq[NPARTX * HD];
__device__ __align__(128) __nv_bfloat16 g_cb1h[(size_t)HD * K1];
__device__ __align__(128) __nv_bfloat16 g_cb1l[(size_t)HD * K1];
__device__ __align__(128) __nv_bfloat16 g_cb2h[(size_t)HD * K2];
__device__ __align__(128) __nv_bfloat16 g_cb2l[(size_t)HD * K2];
__device__ float  g_h1[(size_t)B_ROWS * HD];
__device__ float  g_h2[(size_t)B_ROWS * HD];
__device__ float  g_cp3[HD * NB];

// ---------------- PTX helpers --------------------------------------------------
__device__ __forceinline__ uint32_t smem_u32(const void* p) {
    uint32_t a;
    asm("{ .reg .u64 t; cvta.to.shared.u64 t, %1; cvt.u32.u64 %0, t; }" : "=r"(a) : "l"(p));
    return a;
}
__device__ __forceinline__ uint32_t sw128(uint32_t b) { return b ^ ((b >> 3) & 0x70u); }
__device__ __forceinline__ void cp16(uint32_t s, const void* g) {
    asm volatile("cp.async.cg.shared.global [%0], [%1], 16;" :: "r"(s), "l"(g));
}
#define CP_COMMIT() asm volatile("cp.async.commit_group;" ::: "memory")

__device__ __forceinline__ void ldmx4(uint32_t* r, uint32_t addr) {
    asm volatile("ldmatrix.sync.aligned.m8n8.x4.shared.b16 {%0,%1,%2,%3}, [%4];"
        : "=r"(r[0]), "=r"(r[1]), "=r"(r[2]), "=r"(r[3]) : "r"(addr));
}
// bf16 operands, fp32 accumulate — PROVEN precision path (rel_err ~1e-4)
__device__ __forceinline__ void mma_f32(float* c, const uint32_t* a, const uint32_t* b) {
    asm("mma.sync.aligned.m16n8k16.row.col.f32.bf16.bf16.f32 "
        "{%0,%1,%2,%3}, {%4,%5,%6,%7}, {%8,%9}, {%0,%1,%2,%3};"
        : "+f"(c[0]), "+f"(c[1]), "+f"(c[2]), "+f"(c[3])
        : "r"(a[0]), "r"(a[1]), "r"(a[2]), "r"(a[3]), "r"(b[0]), "r"(b[1]));
}
// packs (lo, hi) floats into bf16x2 word, lo at low half (RN)
__device__ __forceinline__ uint32_t bf16pack(float lo, float hi) {
    uint32_t w;
    asm("cvt.rn.bf16x2.f32 %0, %1, %2;" : "=r"(w) : "f"(hi), "f"(lo));
    return w;
}

// ---------------- stats core ----------------------------------------------------
__device__ __forceinline__ void stats_part_body(const float* __restrict__ src, int C,
                                                int bid, int tid) {
    const int rows = B_ROWS / NPARTX;   // 16
    const int r0 = bid * rows;
    float s = 0.f, q = 0.f;
    for (int rr = 0; rr < rows; rr++) {
        float v = src[(size_t)(r0 + rr) * C + tid];
        s += v;
        q = fmaf(v, v, q);
    }
    g_ps[bid * C + tid] = s;
    g_pq[bid * C + tid] = q;
}

// one block per column, 128 threads: stride-P partial sums + tree reduce
__global__ void k_stats_fin(int C, int P, float* __restrict__ mu, float* __restrict__ inv) {
    int c = blockIdx.x;
    int t = threadIdx.x, lane = t & 31, wrp = t >> 5;
    float s = 0.f, q = 0.f;
    for (int k = t; k < P; k += 128) { s += g_ps[k * C + c]; q += g_pq[k * C + c]; }
#pragma unroll
    for (int off = 16; off; off >>= 1) {
        s += __shfl_xor_sync(0xffffffffu, s, off);
        q += __shfl_xor_sync(0xffffffffu, q, off);
    }
    __shared__ float ss[4], qq[4];
    if (lane == 0) { ss[wrp] = s; qq[wrp] = q; }
    __syncthreads();
    if (t == 0) {
        float S = ss[0] + ss[1] + ss[2] + ss[3];
        float Q = qq[0] + qq[1] + qq[2] + qq[3];
        float m = S / (float)B_ROWS;
        float var = (Q - S * m) / (float)(B_ROWS - 1);
        float sd = sqrtf(fmaxf(var, 0.f));
        mu[c] = m;
        inv[c] = 1.f / (sd + 1e-6f);
    }
}

// ---------------- coeff split (bf16 hi/lo, Kn folded) ----------------------------
__device__ __forceinline__ void coeff_split_body(const float* __restrict__ src, int K,
        __nv_bfloat16* __restrict__ Bh, __nv_bfloat16* __restrict__ Bl, int o, int tid) {
    for (int k = tid; k < K; k += 256) {
        int n = k & 15;
        float cn = fmaf((float)n, 4.f / 15.f, -2.f);
        float Kn = expf(-2.f * cn * cn);
        float v = src[(size_t)o * K + k] * Kn;
        __nv_bfloat16 h = __float2bfloat16(v);
        Bh[(size_t)o * K + k] = h;
        Bl[(size_t)o * K + k] = __float2bfloat16(v - __bfloat162float(h));
    }
}

// fused: stats_part(x) + coeff_split(c1) + coeff_split(c2) + coeffs3
__global__ void k_prep0(const float* __restrict__ x, const float* __restrict__ c1,
                        const float* __restrict__ c2, const float* __restrict__ c3,
                        __nv_bfloat16* __restrict__ cb1h, __nv_bfloat16* __restrict__ cb1l,
                        __nv_bfloat16* __restrict__ cb2h, __nv_bfloat16* __restrict__ cb2l,
                        float* __restrict__ cp3) {
    int bid = blockIdx.x, tid = threadIdx.x;
    if (bid < NPARTX) {
        stats_part_body(x, IN1, bid, tid);
    } else if (bid < NPARTX + HD) {
        coeff_split_body(c1, K1, cb1h, cb1l, bid - NPARTX, tid);
    } else if (bid < NPARTX + 2 * HD) {
        coeff_split_body(c2, K2, cb2h, cb2l, bid - NPARTX - HD, tid);
    } else {
        for (int w = tid; w < HD * NB; w += 256) {
            int i = w >> 4, j = w & 15;
            int n = 15 - j;
            float cn = fmaf((float)n, 4.f / 15.f, -2.f);
            float Kn = expf(-2.f * cn * cn);
            cp3[i * NB + j] = c3[(size_t)i * NB + n] * Kn;
        }
    }
}

// ---------------- fused basis-gen + split-bf16 GEMM + tanh + stats ---------------
__device__ __forceinline__ void load_B(uint32_t stage_base,
        const __nv_bfloat16* __restrict__ Bh, const __nv_bfloat16* __restrict__ Bl,
        int on0, int k0, int K, int tid) {
#pragma unroll
    for (int q = 0; q < 4; q++) {
        int e = tid + (q << 8);
        int row = e >> 3, ch = e & 7;
        uint32_t so = sw128((uint32_t)(row << 7) + (ch << 4));
        size_t gb = (size_t)(on0 + row) * K + k0 + (ch << 3);
        cp16(stage_base + so, Bh + gb);
        cp16(stage_base + B_LO + so, Bl + gb);
    }
}

__device__ __forceinline__ void gen_pair(char* smem, int p, uint32_t src_slot,
        uint32_t abuf, int i0, const float* __restrict__ mu,
        const float* __restrict__ inv) {
    int row = p >> 2, icol = p & 3;
    float v = reinterpret_cast<const float*>(smem + SRC_BASE + src_slot * SRC_SLOT)
                  [(row << 2) + icol];
    int i = i0 + icol;
    float xn = (v - __ldg(mu + i)) * __ldg(inv + i);
    xn = fminf(3.f, fmaxf(-3.f, xn));
    float t = __expf(fmaf(-2.f * xn, xn, -8.f * xn));
    float r = __expf(xn * (16.f / 15.f));
    uint32_t wh[8], wl[8];
    float pv = t;
#pragma unroll
    for (int m = 0; m < 8; m++) {
        float p0 = pv;
        float p1 = pv * r;
        pv = p1 * r;
        uint32_t w = bf16pack(p0, p1);
        wh[m] = w;
        float h0 = __uint_as_float(w << 16);
        float h1 = __uint_as_float(w & 0xffff0000u);
        wl[m] = bf16pack(p0 - h0, p1 - h1);
    }
    uint32_t base = (uint32_t)(row << 7) + (icol << 5);
    uint32_t a0 = sw128(base), a1 = sw128(base + 16);
    *reinterpret_cast<uint4*>(smem + abuf + a0) = make_uint4(wh[0], wh[1], wh[2], wh[3]);
    *reinterpret_cast<uint4*>(smem + abuf + a1) = make_uint4(wh[4], wh[5], wh[6], wh[7]);
    *reinterpret_cast<uint4*>(smem + abuf + AB_LO + a0) = make_uint4(wl[0], wl[1], wl[2], wl[3]);
    *reinterpret_cast<uint4*>(smem + abuf + AB_LO + a1) = make_uint4(wl[4], wl[5], wl[6], wl[7]);
}

__global__ void __launch_bounds__(256, 1)
k_gemm(const float* __restrict__ src, const float* __restrict__ mu,
       const float* __restrict__ inv,
       const __nv_bfloat16* __restrict__ Bh, const __nv_bfloat16* __restrict__ Bl,
       float* __restrict__ out, int K, int C) {
    extern __shared__ __align__(1024) char smem_raw[];
    const uint32_t base = smem_u32(smem_raw);
    const int tid = threadIdx.x;
    const int lane = tid & 31, wid = tid >> 5;
    const int wr = wid & 1, wc = wid >> 1;
    const int bm0 = blockIdx.y << 7, on0 = blockIdx.x << 7;
    const int NCH = K >> 6;

    float acc[4][4][4];
#pragma unroll
    for (int mt = 0; mt < 4; mt++)
#pragma unroll
        for (int nt = 0; nt < 4; nt++)
#pragma unroll
            for (int e = 0; e < 4; e++) acc[mt][nt][e] = 0.f;

    load_B(base + B_BASE, Bh, Bl, on0, 0, K, tid);
    if (tid < 128) cp16(base + SRC_BASE + (tid << 4),
                        src + (size_t)(bm0 + tid) * C);
    CP_COMMIT();
    load_B(base + B_BASE + B_STAGE, Bh, Bl, on0, BK, K, tid);
    if (tid < 128) cp16(base + SRC_BASE + SRC_SLOT + (tid << 4),
                        src + (size_t)(bm0 + tid) * C + 4);
    CP_COMMIT();
    asm volatile("cp.async.wait_group 1;" ::: "memory");
    __syncthreads();
    gen_pair(smem_raw, tid * 2,     0, 0, 0, mu, inv);
    gen_pair(smem_raw, tid * 2 + 1, 0, 0, 0, mu, inv);

    const int g = lane >> 3, lr = lane & 7;

    for (int c = 0; c < NCH; c++) {
        asm volatile("cp.async.wait_group 0;" ::: "memory");
        __syncthreads();

        if (c + 2 < NCH) {
            int s = (c + 2) % 3;
            load_B(base + B_BASE + (uint32_t)s * B_STAGE, Bh, Bl, on0, (c + 2) << 6, K, tid);
            if (tid < 128) cp16(base + SRC_BASE + (uint32_t)s * SRC_SLOT + (tid << 4),
                                src + (size_t)(bm0 + tid) * C + ((c + 2) << 2));
            CP_COMMIT();
        }

        const uint32_t abuf = (uint32_t)(c & 1) * AB_BYTES;
        const uint32_t bst  = B_BASE + (uint32_t)(c % 3) * B_STAGE;
        const bool do_gen = (c + 1 < NCH);
        const uint32_t gslot = (uint32_t)((c + 1) % 3);
        const uint32_t gbuf = (uint32_t)((c + 1) & 1) * AB_BYTES;
        const int gi0 = (c + 1) << 2;

#pragma unroll
        for (int kk = 0; kk < 4; kk++) {
            uint32_t afh[4][4], afl[4][4];
#pragma unroll
            for (int mt = 0; mt < 4; mt++) {
                int m_local = wr * 64 + mt * 16 + (g & 1) * 8 + lr;
                uint32_t off = sw128((uint32_t)(m_local << 7) + (kk << 5) + ((g >> 1) << 4));
                ldmx4(afh[mt], base + abuf + off);
                ldmx4(afl[mt], base + abuf + AB_LO + off);
            }
            uint32_t bfh[2][4], bfl[2][4];
#pragma unroll
            for (int n2 = 0; n2 < 2; n2++) {
                int n_local = wc * 32 + n2 * 16 + (g >> 1) * 8 + lr;
                uint32_t off = sw128((uint32_t)(n_local << 7) + (kk << 5) + ((g & 1) << 4));
                ldmx4(bfh[n2], base + bst + off);
                ldmx4(bfl[n2], base + bst + B_LO + off);
            }
            // term-major: per-acc order preserved (hi*Bh, hi*Bl, lo*Bh), fp32 acc
#pragma unroll
            for (int term = 0; term < 3; term++)
#pragma unroll
                for (int mt = 0; mt < 4; mt++)
#pragma unroll
                    for (int nt = 0; nt < 4; nt++) {
                        const uint32_t* A = (term == 2) ? afl[mt] : afh[mt];
                        const uint32_t* B = (term == 1)
                            ? &bfl[nt >> 1][(nt & 1) * 2]
                            : &bfh[nt >> 1][(nt & 1) * 2];
                        mma_f32(acc[mt][nt], A, B);
                    }

            if (kk == 1 && do_gen) gen_pair(smem_raw, tid * 2,     gslot, gbuf, gi0, mu, inv);
            if (kk == 3 && do_gen) gen_pair(smem_raw, tid * 2 + 1, gslot, gbuf, gi0, mu, inv);
        }
    }

    // epilogue: tanh + store + column-stats partials
    float s_e[4][2], q_e[4][2];
#pragma unroll
    for (int nt = 0; nt < 4; nt++) { s_e[nt][0] = s_e[nt][1] = 0.f; q_e[nt][0] = q_e[nt][1] = 0.f; }

#pragma unroll
    for (int mt = 0; mt < 4; mt++) {
        int row0 = bm0 + wr * 64 + mt * 16 + (lane >> 2);
#pragma unroll
        for (int nt = 0; nt < 4; nt++) {
            int col = on0 + wc * 32 + nt * 8 + (lane & 3) * 2;
            float2 v0, v1;
            v0.x = tanhf(acc[mt][nt][0]);
            v0.y = tanhf(acc[mt][nt][1]);
            v1.x = tanhf(acc[mt][nt][2]);
            v1.y = tanhf(acc[mt][nt][3]);
            *reinterpret_cast<float2*>(out + (size_t)row0 * HD + col) = v0;
            *reinterpret_cast<float2*>(out + (size_t)(row0 + 8) * HD + col) = v1;
            s_e[nt][0] += v0.x + v1.x;  s_e[nt][1] += v0.y + v1.y;
            q_e[nt][0] += v0.x * v0.x + v1.x * v1.x;
            q_e[nt][1] += v0.y * v0.y + v1.y * v1.y;
        }
    }
    float* s_buf = reinterpret_cast<float*>(smem_raw + STAT_BASE);          // [2][128]
    float* q_buf = reinterpret_cast<float*>(smem_raw + STAT_BASE + 1024);   // [2][128]
#pragma unroll
    for (int nt = 0; nt < 4; nt++)
#pragma unroll
        for (int j = 0; j < 2; j++) {
            float s = s_e[nt][j], q = q_e[nt][j];
#pragma unroll
            for (int off = 4; off < 32; off <<= 1) {
                s += __shfl_xor_sync(0xffffffffu, s, off);
                q += __shfl_xor_sync(0xffffffffu, q, off);
            }
            if (lane < 4) {
                int colL = wc * 32 + nt * 8 + lane * 2 + j;
                s_buf[wr * 128 + colL] = s;
                q_buf[wr * 128 + colL] = q;
            }
        }
    __syncthreads();
    if (tid < 128) {
        g_ps[blockIdx.y * HD + on0 + tid] = s_buf[tid] + s_buf[128 + tid];
        g_pq[blockIdx.y * HD + on0 + tid] = q_buf[tid] + q_buf[128 + tid];
    }
}

// ---------------- final layer: t,r inline + Horner + skip ------------------------
__global__ void k_final(const float* __restrict__ h2, const float* __restrict__ mu,
                        const float* __restrict__ inv, const float* __restrict__ cp3,
                        const float* __restrict__ x, const float* __restrict__ sw,
                        const float* __restrict__ sb, float* __restrict__ out) {
    int warp = threadIdx.x >> 5, lane = threadIdx.x & 31;
    int b = blockIdx.x * 8 + warp;
    float acc = 0.f;
    for (int i = lane; i < HD; i += 32) {
        float xn = (h2[(size_t)b * HD + i] - mu[i]) * inv[i];
        xn = fminf(3.f, fmaxf(-3.f, xn));
        float t = __expf(fmaf(-2.f * xn, xn, -8.f * xn));
        float r = __expf(xn * (16.f / 15.f));
        const float* c = &cp3[i * NB];
        float p = c[0];
#pragma unroll
        for (int j = 1; j < NB; j++) p = fmaf(p, r, c[j]);
        acc = fmaf(t, p, acc);
    }
    for (int cidx = lane; cidx < IN1; cidx += 32)
        acc = fmaf(x[(size_t)b * IN1 + cidx], sw[cidx], acc);
#pragma unroll
    for (int off = 16; off; off >>= 1) acc += __shfl_xor_sync(0xffffffffu, acc, off);
    if (lane == 0) out[b] = acc + sb[0];
}

// ---------------- launch ---------------------------------------------------------
extern "C" void kernel_launch(void* const* d_in, const int* in_sizes, int n_in,
                              void* d_out, int out_size) {
    const float* x  = (const float*)d_in[0];
    const float* c1 = (const float*)d_in[1];
    const float* c2 = (const float*)d_in[2];
    const float* c3 = (const float*)d_in[3];
    const float* sw = (const float*)d_in[4];
    const float* sb = (const float*)d_in[5];
    float* out = (float*)d_out;

    __nv_bfloat16 *cb1h, *cb1l, *cb2h, *cb2l;
    float *h1, *h2, *cp3, *mu1, *inv1, *mu2, *inv2, *mu3, *inv3;
    cudaGetSymbolAddress((void**)&cb1h, g_cb1h);
    cudaGetSymbolAddress((void**)&cb1l, g_cb1l);
    cudaGetSymbolAddress((void**)&cb2h, g_cb2h);
    cudaGetSymbolAddress((void**)&cb2l, g_cb2l);
    cudaGetSymbolAddress((void**)&h1,   g_h1);
    cudaGetSymbolAddress((void**)&h2,   g_h2);
    cudaGetSymbolAddress((void**)&cp3,  g_cp3);
    cudaGetSymbolAddress((void**)&mu1,  g_mu1);
    cudaGetSymbolAddress((void**)&inv1, g_inv1);
    cudaGetSymbolAddress((void**)&mu2,  g_mu2);
    cudaGetSymbolAddress((void**)&inv2, g_inv2);
    cudaGetSymbolAddress((void**)&mu3,  g_mu3);
    cudaGetSymbolAddress((void**)&inv3, g_inv3);

    cudaFuncSetAttribute(k_gemm, cudaFuncAttributeMaxDynamicSharedMemorySize, GEMM_SMEM);

    // 0: fused stats(x) + c1 split + c2 split + c3 transform
    k_prep0<<<NPARTX + 2 * HD + 1, 256>>>(x, c1, c2, c3, cb1h, cb1l, cb2h, cb2l, cp3);
    // 1: parallel stats_fin(x)
    k_stats_fin<<<IN1, 128>>>(IN1, NPARTX, mu1, inv1);
    // 2: fused basis+GEMM layer 1 (writes h1 + its column-stat partials)
    k_gemm<<<dim3(HD / BN, B_ROWS / BM), 256, GEMM_SMEM>>>(x, mu1, inv1,
                                                           cb1h, cb1l, h1, K1, IN1);
    k_stats_fin<<<HD, 128>>>(HD, NPARTH, mu2, inv2);
    // layer 2 (writes h2 + partials)
    k_gemm<<<dim3(HD / BN, B_ROWS / BM), 256, GEMM_SMEM>>>(h1, mu2, inv2,
                                                           cb2h, cb2l, h2, K2, HD);
    k_stats_fin<<<HD, 128>>>(HD, NPARTH, mu3, inv3);
    // layer 3 + skip
    k_final<<<B_ROWS / 8, 256>>>(h2, mu3, inv3, cp3, x, sw, sb, out);
}

// round 15
// speedup vs baseline: 1.1945x; 1.0006x over previous
#include <cuda_runtime.h>
#include <cuda_bf16.h>
#include <math.h>
#include <stdint.h>

#define B_ROWS 16384
#define IN1    256
#define HD     512
#define NB     16
#define NPARTX 1024          // partials for x stats
#define NPARTH 128           // partials for h stats (= GEMM grid.y)
#define K1     (IN1 * NB)    // 4096
#define K2     (HD * NB)     // 8192

// GEMM: CTA 128x128, 8 warps (2x4), warp tile 64x32, BK=64
#define BM 128
#define BN 128
#define BK 64
#define AB_BYTES   32768
#define AB_LO      16384
#define B_BASE     65536
#define B_STAGE    32768
#define B_LO       16384
#define SRC_BASE   (B_BASE + 3 * B_STAGE)    // 163840
#define SRC_SLOT   2048
#define STAT_BASE  (SRC_BASE + 3 * SRC_SLOT) // 169984  (2x128 floats s + q)
#define GEMM_SMEM  (STAT_BASE + 4096)        // 174080

// ---------------- scratch (device globals) -----------------------------------
__device__ float g_mu1[IN1], g_inv1[IN1];
__device__ float g_mu2[HD],  g_inv2[HD];
__device__ float g_mu3[HD],  g_inv3[HD];
__device__ float g_ps[NPARTX * HD];
__device__ float g_pq[NPARTX * HD];
__device__ __align__(128) __nv_bfloat16 g_cb1h[(size_t)HD * K1];
__device__ __align__(128) __nv_bfloat16 g_cb1l[(size_t)HD * K1];
__device__ __align__(128) __nv_bfloat16 g_cb2h[(size_t)HD * K2];
__device__ __align__(128) __nv_bfloat16 g_cb2l[(size_t)HD * K2];
__device__ float  g_h1[(size_t)B_ROWS * HD];
__device__ float  g_h2[(size_t)B_ROWS * HD];
__device__ float  g_cp3[HD * NB];

// ---------------- PTX helpers --------------------------------------------------
__device__ __forceinline__ uint32_t smem_u32(const void* p) {
    uint32_t a;
    asm("{ .reg .u64 t; cvta.to.shared.u64 t, %1; cvt.u32.u64 %0, t; }" : "=r"(a) : "l"(p));
    return a;
}
__device__ __forceinline__ uint32_t sw128(uint32_t b) { return b ^ ((b >> 3) & 0x70u); }
__device__ __forceinline__ void cp16(uint32_t s, const void* g) {
    asm volatile("cp.async.cg.shared.global [%0], [%1], 16;" :: "r"(s), "l"(g));
}
#define CP_COMMIT() asm volatile("cp.async.commit_group;" ::: "memory")

__device__ __forceinline__ void ldmx4(uint32_t* r, uint32_t addr) {
    asm volatile("ldmatrix.sync.aligned.m8n8.x4.shared.b16 {%0,%1,%2,%3}, [%4];"
        : "=r"(r[0]), "=r"(r[1]), "=r"(r[2]), "=r"(r[3]) : "r"(addr));
}
// bf16 operands, fp32 accumulate — PROVEN precision path (rel_err ~1e-4)
__device__ __forceinline__ void mma_f32(float* c, const uint32_t* a, const uint32_t* b) {
    asm("mma.sync.aligned.m16n8k16.row.col.f32.bf16.bf16.f32 "
        "{%0,%1,%2,%3}, {%4,%5,%6,%7}, {%8,%9}, {%0,%1,%2,%3};"
        : "+f"(c[0]), "+f"(c[1]), "+f"(c[2]), "+f"(c[3])
        : "r"(a[0]), "r"(a[1]), "r"(a[2]), "r"(a[3]), "r"(b[0]), "r"(b[1]));
}
// packs (lo, hi) floats into bf16x2 word, lo at low half (RN)
__device__ __forceinline__ uint32_t bf16pack(float lo, float hi) {
    uint32_t w;
    asm("cvt.rn.bf16x2.f32 %0, %1, %2;" : "=r"(w) : "f"(hi), "f"(lo));
    return w;
}

// ---------------- stats core ----------------------------------------------------
__device__ __forceinline__ void stats_part_body(const float* __restrict__ src, int C,
                                                int bid, int tid) {
    const int rows = B_ROWS / NPARTX;   // 16
    const int r0 = bid * rows;
    float s = 0.f, q = 0.f;
    for (int rr = 0; rr < rows; rr++) {
        float v = src[(size_t)(r0 + rr) * C + tid];
        s += v;
        q = fmaf(v, v, q);
    }
    g_ps[bid * C + tid] = s;
    g_pq[bid * C + tid] = q;
}

// one block per column, 128 threads: stride-P partial sums + tree reduce
__global__ void k_stats_fin(int C, int P, float* __restrict__ mu, float* __restrict__ inv) {
    int c = blockIdx.x;
    int t = threadIdx.x, lane = t & 31, wrp = t >> 5;
    float s = 0.f, q = 0.f;
    for (int k = t; k < P; k += 128) { s += g_ps[k * C + c]; q += g_pq[k * C + c]; }
#pragma unroll
    for (int off = 16; off; off >>= 1) {
        s += __shfl_xor_sync(0xffffffffu, s, off);
        q += __shfl_xor_sync(0xffffffffu, q, off);
    }
    __shared__ float ss[4], qq[4];
    if (lane == 0) { ss[wrp] = s; qq[wrp] = q; }
    __syncthreads();
    if (t == 0) {
        float S = ss[0] + ss[1] + ss[2] + ss[3];
        float Q = qq[0] + qq[1] + qq[2] + qq[3];
        float m = S / (float)B_ROWS;
        float var = (Q - S * m) / (float)(B_ROWS - 1);
        float sd = sqrtf(fmaxf(var, 0.f));
        mu[c] = m;
        inv[c] = 1.f / (sd + 1e-6f);
    }
}

// ---------------- coeff split (bf16 hi/lo, Kn folded) ----------------------------
__device__ __forceinline__ void coeff_split_body(const float* __restrict__ src, int K,
        __nv_bfloat16* __restrict__ Bh, __nv_bfloat16* __restrict__ Bl, int o, int tid) {
    for (int k = tid; k < K; k += 256) {
        int n = k & 15;
        float cn = fmaf((float)n, 4.f / 15.f, -2.f);
        float Kn = expf(-2.f * cn * cn);
        float v = src[(size_t)o * K + k] * Kn;
        __nv_bfloat16 h = __float2bfloat16(v);
        Bh[(size_t)o * K + k] = h;
        Bl[(size_t)o * K + k] = __float2bfloat16(v - __bfloat162float(h));
    }
}

// fused: stats_part(x) + coeff_split(c1) + coeff_split(c2) + coeffs3
__global__ void k_prep0(const float* __restrict__ x, const float* __restrict__ c1,
                        const float* __restrict__ c2, const float* __restrict__ c3,
                        __nv_bfloat16* __restrict__ cb1h, __nv_bfloat16* __restrict__ cb1l,
                        __nv_bfloat16* __restrict__ cb2h, __nv_bfloat16* __restrict__ cb2l,
                        float* __restrict__ cp3) {
    int bid = blockIdx.x, tid = threadIdx.x;
    if (bid < NPARTX) {
        stats_part_body(x, IN1, bid, tid);
    } else if (bid < NPARTX + HD) {
        coeff_split_body(c1, K1, cb1h, cb1l, bid - NPARTX, tid);
    } else if (bid < NPARTX + 2 * HD) {
        coeff_split_body(c2, K2, cb2h, cb2l, bid - NPARTX - HD, tid);
    } else {
        for (int w = tid; w < HD * NB; w += 256) {
            int i = w >> 4, j = w & 15;
            int n = 15 - j;
            float cn = fmaf((float)n, 4.f / 15.f, -2.f);
            float Kn = expf(-2.f * cn * cn);
            cp3[i * NB + j] = c3[(size_t)i * NB + n] * Kn;
        }
    }
}

// ---------------- fused basis-gen + split-bf16 GEMM + tanh + stats ---------------
__device__ __forceinline__ void load_B(uint32_t stage_base,
        const __nv_bfloat16* __restrict__ Bh, const __nv_bfloat16* __restrict__ Bl,
        int on0, int k0, int K, int tid) {
#pragma unroll
    for (int q = 0; q < 4; q++) {
        int e = tid + (q << 8);
        int row = e >> 3, ch = e & 7;
        uint32_t so = sw128((uint32_t)(row << 7) + (ch << 4));
        size_t gb = (size_t)(on0 + row) * K + k0 + (ch << 3);
        cp16(stage_base + so, Bh + gb);
        cp16(stage_base + B_LO + so, Bl + gb);
    }
}

__device__ __forceinline__ void gen_pair(char* smem, int p, uint32_t src_slot,
        uint32_t abuf, int i0, const float* __restrict__ mu,
        const float* __restrict__ inv) {
    int row = p >> 2, icol = p & 3;
    float v = reinterpret_cast<const float*>(smem + SRC_BASE + src_slot * SRC_SLOT)
                  [(row << 2) + icol];
    int i = i0 + icol;
    float xn = (v - __ldg(mu + i)) * __ldg(inv + i);
    xn = fminf(3.f, fmaxf(-3.f, xn));
    float t = __expf(fmaf(-2.f * xn, xn, -8.f * xn));
    float r = __expf(xn * (16.f / 15.f));
    uint32_t wh[8], wl[8];
    float pv = t;
#pragma unroll
    for (int m = 0; m < 8; m++) {
        float p0 = pv;
        float p1 = pv * r;
        pv = p1 * r;
        uint32_t w = bf16pack(p0, p1);
        wh[m] = w;
        float h0 = __uint_as_float(w << 16);
        float h1 = __uint_as_float(w & 0xffff0000u);
        wl[m] = bf16pack(p0 - h0, p1 - h1);
    }
    uint32_t base = (uint32_t)(row << 7) + (icol << 5);
    uint32_t a0 = sw128(base), a1 = sw128(base + 16);
    *reinterpret_cast<uint4*>(smem + abuf + a0) = make_uint4(wh[0], wh[1], wh[2], wh[3]);
    *reinterpret_cast<uint4*>(smem + abuf + a1) = make_uint4(wh[4], wh[5], wh[6], wh[7]);
    *reinterpret_cast<uint4*>(smem + abuf + AB_LO + a0) = make_uint4(wl[0], wl[1], wl[2], wl[3]);
    *reinterpret_cast<uint4*>(smem + abuf + AB_LO + a1) = make_uint4(wl[4], wl[5], wl[6], wl[7]);
}

__global__ void __launch_bounds__(256, 1)
k_gemm(const float* __restrict__ src, const float* __restrict__ mu,
       const float* __restrict__ inv,
       const __nv_bfloat16* __restrict__ Bh, const __nv_bfloat16* __restrict__ Bl,
       float* __restrict__ out, int K, int C) {
    extern __shared__ __align__(1024) char smem_raw[];
    const uint32_t base = smem_u32(smem_raw);
    const int tid = threadIdx.x;
    const int lane = tid & 31, wid = tid >> 5;
    const int wr = wid & 1, wc = wid >> 1;
    const int bm0 = blockIdx.y << 7, on0 = blockIdx.x << 7;
    const int NCH = K >> 6;

    float acc[4][4][4];
#pragma unroll
    for (int mt = 0; mt < 4; mt++)
#pragma unroll
        for (int nt = 0; nt < 4; nt++)
#pragma unroll
            for (int e = 0; e < 4; e++) acc[mt][nt][e] = 0.f;

    load_B(base + B_BASE, Bh, Bl, on0, 0, K, tid);
    if (tid < 128) cp16(base + SRC_BASE + (tid << 4),
                        src + (size_t)(bm0 + tid) * C);
    CP_COMMIT();
    load_B(base + B_BASE + B_STAGE, Bh, Bl, on0, BK, K, tid);
    if (tid < 128) cp16(base + SRC_BASE + SRC_SLOT + (tid << 4),
                        src + (size_t)(bm0 + tid) * C + 4);
    CP_COMMIT();
    asm volatile("cp.async.wait_group 1;" ::: "memory");
    __syncthreads();
    gen_pair(smem_raw, tid * 2,     0, 0, 0, mu, inv);
    gen_pair(smem_raw, tid * 2 + 1, 0, 0, 0, mu, inv);

    const int g = lane >> 3, lr = lane & 7;

    for (int c = 0; c < NCH; c++) {
        asm volatile("cp.async.wait_group 0;" ::: "memory");
        __syncthreads();

        if (c + 2 < NCH) {
            int s = (c + 2) % 3;
            load_B(base + B_BASE + (uint32_t)s * B_STAGE, Bh, Bl, on0, (c + 2) << 6, K, tid);
            if (tid < 128) cp16(base + SRC_BASE + (uint32_t)s * SRC_SLOT + (tid << 4),
                                src + (size_t)(bm0 + tid) * C + ((c + 2) << 2));
            CP_COMMIT();
        }

        const uint32_t abuf = (uint32_t)(c & 1) * AB_BYTES;
        const uint32_t bst  = B_BASE + (uint32_t)(c % 3) * B_STAGE;
        const bool do_gen = (c + 1 < NCH);
        const uint32_t gslot = (uint32_t)((c + 1) % 3);
        const uint32_t gbuf = (uint32_t)((c + 1) & 1) * AB_BYTES;
        const int gi0 = (c + 1) << 2;

#pragma unroll
        for (int kk = 0; kk < 4; kk++) {
            uint32_t afh[4][4], afl[4][4];
#pragma unroll
            for (int mt = 0; mt < 4; mt++) {
                int m_local = wr * 64 + mt * 16 + (g & 1) * 8 + lr;
                uint32_t off = sw128((uint32_t)(m_local << 7) + (kk << 5) + ((g >> 1) << 4));
                ldmx4(afh[mt], base + abuf + off);
                ldmx4(afl[mt], base + abuf + AB_LO + off);
            }
            uint32_t bfh[2][4], bfl[2][4];
#pragma unroll
            for (int n2 = 0; n2 < 2; n2++) {
                int n_local = wc * 32 + n2 * 16 + (g >> 1) * 8 + lr;
                uint32_t off = sw128((uint32_t)(n_local << 7) + (kk << 5) + ((g & 1) << 4));
                ldmx4(bfh[n2], base + bst + off);
                ldmx4(bfl[n2], base + bst + B_LO + off);
            }
            // term-major: per-acc order preserved (hi*Bh, hi*Bl, lo*Bh), fp32 acc
#pragma unroll
            for (int term = 0; term < 3; term++)
#pragma unroll
                for (int mt = 0; mt < 4; mt++)
#pragma unroll
                    for (int nt = 0; nt < 4; nt++) {
                        const uint32_t* A = (term == 2) ? afl[mt] : afh[mt];
                        const uint32_t* B = (term == 1)
                            ? &bfl[nt >> 1][(nt & 1) * 2]
                            : &bfh[nt >> 1][(nt & 1) * 2];
                        mma_f32(acc[mt][nt], A, B);
                    }

            if (kk == 1 && do_gen) gen_pair(smem_raw, tid * 2,     gslot, gbuf, gi0, mu, inv);
            if (kk == 3 && do_gen) gen_pair(smem_raw, tid * 2 + 1, gslot, gbuf, gi0, mu, inv);
        }
    }

    // epilogue: tanh + store + column-stats partials
    float s_e[4][2], q_e[4][2];
#pragma unroll
    for (int nt = 0; nt < 4; nt++) { s_e[nt][0] = s_e[nt][1] = 0.f; q_e[nt][0] = q_e[nt][1] = 0.f; }

#pragma unroll
    for (int mt = 0; mt < 4; mt++) {
        int row0 = bm0 + wr * 64 + mt * 16 + (lane >> 2);
#pragma unroll
        for (int nt = 0; nt < 4; nt++) {
            int col = on0 + wc * 32 + nt * 8 + (lane & 3) * 2;
            float2 v0, v1;
            v0.x = tanhf(acc[mt][nt][0]);
            v0.y = tanhf(acc[mt][nt][1]);
            v1.x = tanhf(acc[mt][nt][2]);
            v1.y = tanhf(acc[mt][nt][3]);
            *reinterpret_cast<float2*>(out + (size_t)row0 * HD + col) = v0;
            *reinterpret_cast<float2*>(out + (size_t)(row0 + 8) * HD + col) = v1;
            s_e[nt][0] += v0.x + v1.x;  s_e[nt][1] += v0.y + v1.y;
            q_e[nt][0] += v0.x * v0.x + v1.x * v1.x;
            q_e[nt][1] += v0.y * v0.y + v1.y * v1.y;
        }
    }
    float* s_buf = reinterpret_cast<float*>(smem_raw + STAT_BASE);          // [2][128]
    float* q_buf = reinterpret_cast<float*>(smem_raw + STAT_BASE + 1024);   // [2][128]
#pragma unroll
    for (int nt = 0; nt < 4; nt++)
#pragma unroll
        for (int j = 0; j < 2; j++) {
            float s = s_e[nt][j], q = q_e[nt][j];
#pragma unroll
            for (int off = 4; off < 32; off <<= 1) {
                s += __shfl_xor_sync(0xffffffffu, s, off);
                q += __shfl_xor_sync(0xffffffffu, q, off);
            }
            if (lane < 4) {
                int colL = wc * 32 + nt * 8 + lane * 2 + j;
                s_buf[wr * 128 + colL] = s;
                q_buf[wr * 128 + colL] = q;
            }
        }
    __syncthreads();
    if (tid < 128) {
        g_ps[blockIdx.y * HD + on0 + tid] = s_buf[tid] + s_buf[128 + tid];
        g_pq[blockIdx.y * HD + on0 + tid] = q_buf[tid] + q_buf[128 + tid];
    }
}

// ---------------- final layer: t,r inline + Horner + skip ------------------------
__global__ void k_final(const float* __restrict__ h2, const float* __restrict__ mu,
                        const float* __restrict__ inv, const float* __restrict__ cp3,
                        const float* __restrict__ x, const float* __restrict__ sw,
                        const float* __restrict__ sb, float* __restrict__ out) {
    int warp = threadIdx.x >> 5, lane = threadIdx.x & 31;
    int b = blockIdx.x * 8 + warp;
    float acc = 0.f;
    for (int i = lane; i < HD; i += 32) {
        float xn = (h2[(size_t)b * HD + i] - mu[i]) * inv[i];
        xn = fminf(3.f, fmaxf(-3.f, xn));
        float t = __expf(fmaf(-2.f * xn, xn, -8.f * xn));
        float r = __expf(xn * (16.f / 15.f));
        const float* c = &cp3[i * NB];
        float p = c[0];
#pragma unroll
        for (int j = 1; j < NB; j++) p = fmaf(p, r, c[j]);
        acc = fmaf(t, p, acc);
    }
    for (int cidx = lane; cidx < IN1; cidx += 32)
        acc = fmaf(x[(size_t)b * IN1 + cidx], sw[cidx], acc);
#pragma unroll
    for (int off = 16; off; off >>= 1) acc += __shfl_xor_sync(0xffffffffu, acc, off);
    if (lane == 0) out[b] = acc + sb[0];
}

// ---------------- launch ---------------------------------------------------------
extern "C" void kernel_launch(void* const* d_in, const int* in_sizes, int n_in,
                              void* d_out, int out_size) {
    const float* x  = (const float*)d_in[0];
    const float* c1 = (const float*)d_in[1];
    const float* c2 = (const float*)d_in[2];
    const float* c3 = (const float*)d_in[3];
    const float* sw = (const float*)d_in[4];
    const float* sb = (const float*)d_in[5];
    float* out = (float*)d_out;

    __nv_bfloat16 *cb1h, *cb1l, *cb2h, *cb2l;
    float *h1, *h2, *cp3, *mu1, *inv1, *mu2, *inv2, *mu3, *inv3;
    cudaGetSymbolAddress((void**)&cb1h, g_cb1h);
    cudaGetSymbolAddress((void**)&cb1l, g_cb1l);
    cudaGetSymbolAddress((void**)&cb2h, g_cb2h);
    cudaGetSymbolAddress((void**)&cb2l, g_cb2l);
    cudaGetSymbolAddress((void**)&h1,   g_h1);
    cudaGetSymbolAddress((void**)&h2,   g_h2);
    cudaGetSymbolAddress((void**)&cp3,  g_cp3);
    cudaGetSymbolAddress((void**)&mu1,  g_mu1);
    cudaGetSymbolAddress((void**)&inv1, g_inv1);
    cudaGetSymbolAddress((void**)&mu2,  g_mu2);
    cudaGetSymbolAddress((void**)&inv2, g_inv2);
    cudaGetSymbolAddress((void**)&mu3,  g_mu3);
    cudaGetSymbolAddress((void**)&inv3, g_inv3);

    cudaFuncSetAttribute(k_gemm, cudaFuncAttributeMaxDynamicSharedMemorySize, GEMM_SMEM);

    // 0: fused stats(x) + c1 split + c2 split + c3 transform
    k_prep0<<<NPARTX + 2 * HD + 1, 256>>>(x, c1, c2, c3, cb1h, cb1l, cb2h, cb2l, cp3);
    // 1: parallel stats_fin(x)
    k_stats_fin<<<IN1, 128>>>(IN1, NPARTX, mu1, inv1);
    // 2: fused basis+GEMM layer 1 (writes h1 + its column-stat partials)
    k_gemm<<<dim3(HD / BN, B_ROWS / BM), 256, GEMM_SMEM>>>(x, mu1, inv1,
                                                           cb1h, cb1l, h1, K1, IN1);
    k_stats_fin<<<HD, 128>>>(HD, NPARTH, mu2, inv2);
    // layer 2 (writes h2 + partials)
    k_gemm<<<dim3(HD / BN, B_ROWS / BM), 256, GEMM_SMEM>>>(h1, mu2, inv2,
                                                           cb2h, cb2l, h2, K2, HD);
    k_stats_fin<<<HD, 128>>>(HD, NPARTH, mu3, inv3);
    // layer 3 + skip
    k_final<<<B_ROWS / 8, 256>>>(h2, mu3, inv3, cp3, x, sw, sb, out);
}

// round 16
// speedup vs baseline: 1.1946x; 1.0001x over previous
#include <cuda_runtime.h>
#include <cuda_bf16.h>
#include <math.h>
#include <stdint.h>

#define B_ROWS 16384
#define IN1    256
#define HD     512
#define NB     16
#define NPARTX 1024          // partials for x stats
#define NPARTH 128           // partials for h stats (= GEMM grid.y)
#define K1     (IN1 * NB)    // 4096
#define K2     (HD * NB)     // 8192

// GEMM: CTA 128x128, 8 warps (2x4), warp tile 64x32, BK=64
#define BM 128
#define BN 128
#define BK 64
#define AB_BYTES   32768
#define AB_LO      16384
#define B_BASE     65536
#define B_STAGE    32768
#define B_LO       16384
#define SRC_BASE   (B_BASE + 3 * B_STAGE)    // 163840
#define SRC_SLOT   2048
#define STAT_BASE  (SRC_BASE + 3 * SRC_SLOT) // 169984  (2x128 floats s + q)
#define GEMM_SMEM  (STAT_BASE + 4096)        // 174080

// ---------------- scratch (device globals) -----------------------------------
__device__ float g_mu1[IN1], g_inv1[IN1];
__device__ float g_mu2[HD],  g_inv2[HD];
__device__ float g_mu3[HD],  g_inv3[HD];
__device__ float g_ps[NPARTX * HD];
__device__ float g_pq[NPARTX * HD];
__device__ __align__(128) __nv_bfloat16 g_cb1h[(size_t)HD * K1];
__device__ __align__(128) __nv_bfloat16 g_cb1l[(size_t)HD * K1];
__device__ __align__(128) __nv_bfloat16 g_cb2h[(size_t)HD * K2];
__device__ __align__(128) __nv_bfloat16 g_cb2l[(size_t)HD * K2];
__device__ float  g_h1[(size_t)B_ROWS * HD];
__device__ float  g_h2[(size_t)B_ROWS * HD];
__device__ float  g_cp3[HD * NB];

// ---------------- PTX helpers --------------------------------------------------
__device__ __forceinline__ uint32_t smem_u32(const void* p) {
    uint32_t a;
    asm("{ .reg .u64 t; cvta.to.shared.u64 t, %1; cvt.u32.u64 %0, t; }" : "=r"(a) : "l"(p));
    return a;
}
__device__ __forceinline__ uint32_t sw128(uint32_t b) { return b ^ ((b >> 3) & 0x70u); }
__device__ __forceinline__ void cp16(uint32_t s, const void* g) {
    asm volatile("cp.async.cg.shared.global [%0], [%1], 16;" :: "r"(s), "l"(g));
}
#define CP_COMMIT() asm volatile("cp.async.commit_group;" ::: "memory")

__device__ __forceinline__ void ldmx4(uint32_t* r, uint32_t addr) {
    asm volatile("ldmatrix.sync.aligned.m8n8.x4.shared.b16 {%0,%1,%2,%3}, [%4];"
        : "=r"(r[0]), "=r"(r[1]), "=r"(r[2]), "=r"(r[3]) : "r"(addr));
}
// bf16 operands, fp32 accumulate — PROVEN precision path (rel_err ~1e-4)
__device__ __forceinline__ void mma_f32(float* c, const uint32_t* a, const uint32_t* b) {
    asm("mma.sync.aligned.m16n8k16.row.col.f32.bf16.bf16.f32 "
        "{%0,%1,%2,%3}, {%4,%5,%6,%7}, {%8,%9}, {%0,%1,%2,%3};"
        : "+f"(c[0]), "+f"(c[1]), "+f"(c[2]), "+f"(c[3])
        : "r"(a[0]), "r"(a[1]), "r"(a[2]), "r"(a[3]), "r"(b[0]), "r"(b[1]));
}
// packs (lo, hi) floats into bf16x2 word, lo at low half (RN)
__device__ __forceinline__ uint32_t bf16pack(float lo, float hi) {
    uint32_t w;
    asm("cvt.rn.bf16x2.f32 %0, %1, %2;" : "=r"(w) : "f"(hi), "f"(lo));
    return w;
}

// ---------------- stats core ----------------------------------------------------
__device__ __forceinline__ void stats_part_body(const float* __restrict__ src, int C,
                                                int bid, int tid) {
    const int rows = B_ROWS / NPARTX;   // 16
    const int r0 = bid * rows;
    float s = 0.f, q = 0.f;
    for (int rr = 0; rr < rows; rr++) {
        float v = src[(size_t)(r0 + rr) * C + tid];
        s += v;
        q = fmaf(v, v, q);
    }
    g_ps[bid * C + tid] = s;
    g_pq[bid * C + tid] = q;
}

// one block per column, 128 threads: stride-P partial sums + tree reduce
__global__ void k_stats_fin(int C, int P, float* __restrict__ mu, float* __restrict__ inv) {
    int c = blockIdx.x;
    int t = threadIdx.x, lane = t & 31, wrp = t >> 5;
    float s = 0.f, q = 0.f;
    for (int k = t; k < P; k += 128) { s += g_ps[k * C + c]; q += g_pq[k * C + c]; }
#pragma unroll
    for (int off = 16; off; off >>= 1) {
        s += __shfl_xor_sync(0xffffffffu, s, off);
        q += __shfl_xor_sync(0xffffffffu, q, off);
    }
    __shared__ float ss[4], qq[4];
    if (lane == 0) { ss[wrp] = s; qq[wrp] = q; }
    __syncthreads();
    if (t == 0) {
        float S = ss[0] + ss[1] + ss[2] + ss[3];
        float Q = qq[0] + qq[1] + qq[2] + qq[3];
        float m = S / (float)B_ROWS;
        float var = (Q - S * m) / (float)(B_ROWS - 1);
        float sd = sqrtf(fmaxf(var, 0.f));
        mu[c] = m;
        inv[c] = 1.f / (sd + 1e-6f);
    }
}

// ---------------- coeff split (bf16 hi/lo, Kn folded) ----------------------------
__device__ __forceinline__ void coeff_split_body(const float* __restrict__ src, int K,
        __nv_bfloat16* __restrict__ Bh, __nv_bfloat16* __restrict__ Bl, int o, int tid) {
    for (int k = tid; k < K; k += 256) {
        int n = k & 15;
        float cn = fmaf((float)n, 4.f / 15.f, -2.f);
        float Kn = expf(-2.f * cn * cn);
        float v = src[(size_t)o * K + k] * Kn;
        __nv_bfloat16 h = __float2bfloat16(v);
        Bh[(size_t)o * K + k] = h;
        Bl[(size_t)o * K + k] = __float2bfloat16(v - __bfloat162float(h));
    }
}

// fused: stats_part(x) + coeff_split(c1) + coeff_split(c2) + coeffs3
__global__ void k_prep0(const float* __restrict__ x, const float* __restrict__ c1,
                        const float* __restrict__ c2, const float* __restrict__ c3,
                        __nv_bfloat16* __restrict__ cb1h, __nv_bfloat16* __restrict__ cb1l,
                        __nv_bfloat16* __restrict__ cb2h, __nv_bfloat16* __restrict__ cb2l,
                        float* __restrict__ cp3) {
    int bid = blockIdx.x, tid = threadIdx.x;
    if (bid < NPARTX) {
        stats_part_body(x, IN1, bid, tid);
    } else if (bid < NPARTX + HD) {
        coeff_split_body(c1, K1, cb1h, cb1l, bid - NPARTX, tid);
    } else if (bid < NPARTX + 2 * HD) {
        coeff_split_body(c2, K2, cb2h, cb2l, bid - NPARTX - HD, tid);
    } else {
        for (int w = tid; w < HD * NB; w += 256) {
            int i = w >> 4, j = w & 15;
            int n = 15 - j;
            float cn = fmaf((float)n, 4.f / 15.f, -2.f);
            float Kn = expf(-2.f * cn * cn);
            cp3[i * NB + j] = c3[(size_t)i * NB + n] * Kn;
        }
    }
}

// ---------------- fused basis-gen + split-bf16 GEMM + tanh + stats ---------------
__device__ __forceinline__ void load_B(uint32_t stage_base,
        const __nv_bfloat16* __restrict__ Bh, const __nv_bfloat16* __restrict__ Bl,
        int on0, int k0, int K, int tid) {
#pragma unroll
    for (int q = 0; q < 4; q++) {
        int e = tid + (q << 8);
        int row = e >> 3, ch = e & 7;
        uint32_t so = sw128((uint32_t)(row << 7) + (ch << 4));
        size_t gb = (size_t)(on0 + row) * K + k0 + (ch << 3);
        cp16(stage_base + so, Bh + gb);
        cp16(stage_base + B_LO + so, Bl + gb);
    }
}

__device__ __forceinline__ void gen_pair(char* smem, int p, uint32_t src_slot,
        uint32_t abuf, int i0, const float* __restrict__ mu,
        const float* __restrict__ inv) {
    int row = p >> 2, icol = p & 3;
    float v = reinterpret_cast<const float*>(smem + SRC_BASE + src_slot * SRC_SLOT)
                  [(row << 2) + icol];
    int i = i0 + icol;
    float xn = (v - __ldg(mu + i)) * __ldg(inv + i);
    xn = fminf(3.f, fmaxf(-3.f, xn));
    float t = __expf(fmaf(-2.f * xn, xn, -8.f * xn));
    float r = __expf(xn * (16.f / 15.f));
    uint32_t wh[8], wl[8];
    float pv = t;
#pragma unroll
    for (int m = 0; m < 8; m++) {
        float p0 = pv;
        float p1 = pv * r;
        pv = p1 * r;
        uint32_t w = bf16pack(p0, p1);
        wh[m] = w;
        float h0 = __uint_as_float(w << 16);
        float h1 = __uint_as_float(w & 0xffff0000u);
        wl[m] = bf16pack(p0 - h0, p1 - h1);
    }
    uint32_t base = (uint32_t)(row << 7) + (icol << 5);
    uint32_t a0 = sw128(base), a1 = sw128(base + 16);
    *reinterpret_cast<uint4*>(smem + abuf + a0) = make_uint4(wh[0], wh[1], wh[2], wh[3]);
    *reinterpret_cast<uint4*>(smem + abuf + a1) = make_uint4(wh[4], wh[5], wh[6], wh[7]);
    *reinterpret_cast<uint4*>(smem + abuf + AB_LO + a0) = make_uint4(wl[0], wl[1], wl[2], wl[3]);
    *reinterpret_cast<uint4*>(smem + abuf + AB_LO + a1) = make_uint4(wl[4], wl[5], wl[6], wl[7]);
}

__global__ void __launch_bounds__(256, 1)
k_gemm(const float* __restrict__ src, const float* __restrict__ mu,
       const float* __restrict__ inv,
       const __nv_bfloat16* __restrict__ Bh, const __nv_bfloat16* __restrict__ Bl,
       float* __restrict__ out, int K, int C) {
    extern __shared__ __align__(1024) char smem_raw[];
    const uint32_t base = smem_u32(smem_raw);
    const int tid = threadIdx.x;
    const int lane = tid & 31, wid = tid >> 5;
    const int wr = wid & 1, wc = wid >> 1;
    const int bm0 = blockIdx.y << 7, on0 = blockIdx.x << 7;
    const int NCH = K >> 6;

    float acc[4][4][4];
#pragma unroll
    for (int mt = 0; mt < 4; mt++)
#pragma unroll
        for (int nt = 0; nt < 4; nt++)
#pragma unroll
            for (int e = 0; e < 4; e++) acc[mt][nt][e] = 0.f;

    load_B(base + B_BASE, Bh, Bl, on0, 0, K, tid);
    if (tid < 128) cp16(base + SRC_BASE + (tid << 4),
                        src + (size_t)(bm0 + tid) * C);
    CP_COMMIT();
    load_B(base + B_BASE + B_STAGE, Bh, Bl, on0, BK, K, tid);
    if (tid < 128) cp16(base + SRC_BASE + SRC_SLOT + (tid << 4),
                        src + (size_t)(bm0 + tid) * C + 4);
    CP_COMMIT();
    asm volatile("cp.async.wait_group 1;" ::: "memory");
    __syncthreads();
    gen_pair(smem_raw, tid * 2,     0, 0, 0, mu, inv);
    gen_pair(smem_raw, tid * 2 + 1, 0, 0, 0, mu, inv);

    const int g = lane >> 3, lr = lane & 7;

    for (int c = 0; c < NCH; c++) {
        asm volatile("cp.async.wait_group 0;" ::: "memory");
        __syncthreads();

        if (c + 2 < NCH) {
            int s = (c + 2) % 3;
            load_B(base + B_BASE + (uint32_t)s * B_STAGE, Bh, Bl, on0, (c + 2) << 6, K, tid);
            if (tid < 128) cp16(base + SRC_BASE + (uint32_t)s * SRC_SLOT + (tid << 4),
                                src + (size_t)(bm0 + tid) * C + ((c + 2) << 2));
            CP_COMMIT();
        }

        const uint32_t abuf = (uint32_t)(c & 1) * AB_BYTES;
        const uint32_t bst  = B_BASE + (uint32_t)(c % 3) * B_STAGE;
        const bool do_gen = (c + 1 < NCH);
        const uint32_t gslot = (uint32_t)((c + 1) % 3);
        const uint32_t gbuf = (uint32_t)((c + 1) & 1) * AB_BYTES;
        const int gi0 = (c + 1) << 2;

#pragma unroll
        for (int kk = 0; kk < 4; kk++) {
            uint32_t afh[4][4], afl[4][4];
#pragma unroll
            for (int mt = 0; mt < 4; mt++) {
                int m_local = wr * 64 + mt * 16 + (g & 1) * 8 + lr;
                uint32_t off = sw128((uint32_t)(m_local << 7) + (kk << 5) + ((g >> 1) << 4));
                ldmx4(afh[mt], base + abuf + off);
                ldmx4(afl[mt], base + abuf + AB_LO + off);
            }
            uint32_t bfh[2][4], bfl[2][4];
#pragma unroll
            for (int n2 = 0; n2 < 2; n2++) {
                int n_local = wc * 32 + n2 * 16 + (g >> 1) * 8 + lr;
                uint32_t off = sw128((uint32_t)(n_local << 7) + (kk << 5) + ((g & 1) << 4));
                ldmx4(bfh[n2], base + bst + off);
                ldmx4(bfl[n2], base + bst + B_LO + off);
            }
            // term-major: per-acc order preserved (hi*Bh, hi*Bl, lo*Bh), fp32 acc
#pragma unroll
            for (int term = 0; term < 3; term++)
#pragma unroll
                for (int mt = 0; mt < 4; mt++)
#pragma unroll
                    for (int nt = 0; nt < 4; nt++) {
                        const uint32_t* A = (term == 2) ? afl[mt] : afh[mt];
                        const uint32_t* B = (term == 1)
                            ? &bfl[nt >> 1][(nt & 1) * 2]
                            : &bfh[nt >> 1][(nt & 1) * 2];
                        mma_f32(acc[mt][nt], A, B);
                    }

            if (kk == 1 && do_gen) gen_pair(smem_raw, tid * 2,     gslot, gbuf, gi0, mu, inv);
            if (kk == 3 && do_gen) gen_pair(smem_raw, tid * 2 + 1, gslot, gbuf, gi0, mu, inv);
        }
    }

    // epilogue: tanh + store + column-stats partials
    float s_e[4][2], q_e[4][2];
#pragma unroll
    for (int nt = 0; nt < 4; nt++) { s_e[nt][0] = s_e[nt][1] = 0.f; q_e[nt][0] = q_e[nt][1] = 0.f; }

#pragma unroll
    for (int mt = 0; mt < 4; mt++) {
        int row0 = bm0 + wr * 64 + mt * 16 + (lane >> 2);
#pragma unroll
        for (int nt = 0; nt < 4; nt++) {
            int col = on0 + wc * 32 + nt * 8 + (lane & 3) * 2;
            float2 v0, v1;
            v0.x = tanhf(acc[mt][nt][0]);
            v0.y = tanhf(acc[mt][nt][1]);
            v1.x = tanhf(acc[mt][nt][2]);
            v1.y = tanhf(acc[mt][nt][3]);
            *reinterpret_cast<float2*>(out + (size_t)row0 * HD + col) = v0;
            *reinterpret_cast<float2*>(out + (size_t)(row0 + 8) * HD + col) = v1;
            s_e[nt][0] += v0.x + v1.x;  s_e[nt][1] += v0.y + v1.y;
            q_e[nt][0] += v0.x * v0.x + v1.x * v1.x;
            q_e[nt][1] += v0.y * v0.y + v1.y * v1.y;
        }
    }
    float* s_buf = reinterpret_cast<float*>(smem_raw + STAT_BASE);          // [2][128]
    float* q_buf = reinterpret_cast<float*>(smem_raw + STAT_BASE + 1024);   // [2][128]
#pragma unroll
    for (int nt = 0; nt < 4; nt++)
#pragma unroll
        for (int j = 0; j < 2; j++) {
            float s = s_e[nt][j], q = q_e[nt][j];
#pragma unroll
            for (int off = 4; off < 32; off <<= 1) {
                s += __shfl_xor_sync(0xffffffffu, s, off);
                q += __shfl_xor_sync(0xffffffffu, q, off);
            }
            if (lane < 4) {
                int colL = wc * 32 + nt * 8 + lane * 2 + j;
                s_buf[wr * 128 + colL] = s;
                q_buf[wr * 128 + colL] = q;
            }
        }
    __syncthreads();
    if (tid < 128) {
        g_ps[blockIdx.y * HD + on0 + tid] = s_buf[tid] + s_buf[128 + tid];
        g_pq[blockIdx.y * HD + on0 + tid] = q_buf[tid] + q_buf[128 + tid];
    }
}

// ---------------- final layer: t,r inline + Horner + skip ------------------------
__global__ void k_final(const float* __restrict__ h2, const float* __restrict__ mu,
                        const float* __restrict__ inv, const float* __restrict__ cp3,
                        const float* __restrict__ x, const float* __restrict__ sw,
                        const float* __restrict__ sb, float* __restrict__ out) {
    int warp = threadIdx.x >> 5, lane = threadIdx.x & 31;
    int b = blockIdx.x * 8 + warp;
    float acc = 0.f;
    for (int i = lane; i < HD; i += 32) {
        float xn = (h2[(size_t)b * HD + i] - mu[i]) * inv[i];
        xn = fminf(3.f, fmaxf(-3.f, xn));
        float t = __expf(fmaf(-2.f * xn, xn, -8.f * xn));
        float r = __expf(xn * (16.f / 15.f));
        const float* c = &cp3[i * NB];
        float p = c[0];
#pragma unroll
        for (int j = 1; j < NB; j++) p = fmaf(p, r, c[j]);
        acc = fmaf(t, p, acc);
    }
    for (int cidx = lane; cidx < IN1; cidx += 32)
        acc = fmaf(x[(size_t)b * IN1 + cidx], sw[cidx], acc);
#pragma unroll
    for (int off = 16; off; off >>= 1) acc += __shfl_xor_sync(0xffffffffu, acc, off);
    if (lane == 0) out[b] = acc + sb[0];
}

// ---------------- launch ---------------------------------------------------------
extern "C" void kernel_launch(void* const* d_in, const int* in_sizes, int n_in,
                              void* d_out, int out_size) {
    const float* x  = (const float*)d_in[0];
    const float* c1 = (const float*)d_in[1];
    const float* c2 = (const float*)d_in[2];
    const float* c3 = (const float*)d_in[3];
    const float* sw = (const float*)d_in[4];
    const float* sb = (const float*)d_in[5];
    float* out = (float*)d_out;

    __nv_bfloat16 *cb1h, *cb1l, *cb2h, *cb2l;
    float *h1, *h2, *cp3, *mu1, *inv1, *mu2, *inv2, *mu3, *inv3;
    cudaGetSymbolAddress((void**)&cb1h, g_cb1h);
    cudaGetSymbolAddress((void**)&cb1l, g_cb1l);
    cudaGetSymbolAddress((void**)&cb2h, g_cb2h);
    cudaGetSymbolAddress((void**)&cb2l, g_cb2l);
    cudaGetSymbolAddress((void**)&h1,   g_h1);
    cudaGetSymbolAddress((void**)&h2,   g_h2);
    cudaGetSymbolAddress((void**)&cp3,  g_cp3);
    cudaGetSymbolAddress((void**)&mu1,  g_mu1);
    cudaGetSymbolAddress((void**)&inv1, g_inv1);
    cudaGetSymbolAddress((void**)&mu2,  g_mu2);
    cudaGetSymbolAddress((void**)&inv2, g_inv2);
    cudaGetSymbolAddress((void**)&mu3,  g_mu3);
    cudaGetSymbolAddress((void**)&inv3, g_inv3);

    cudaFuncSetAttribute(k_gemm, cudaFuncAttributeMaxDynamicSharedMemorySize, GEMM_SMEM);

    // 0: fused stats(x) + c1 split + c2 split + c3 transform
    k_prep0<<<NPARTX + 2 * HD + 1, 256>>>(x, c1, c2, c3, cb1h, cb1l, cb2h, cb2l, cp3);
    // 1: parallel stats_fin(x)
    k_stats_fin<<<IN1, 128>>>(IN1, NPARTX, mu1, inv1);
    // 2: fused basis+GEMM layer 1 (writes h1 + its column-stat partials)
    k_gemm<<<dim3(HD / BN, B_ROWS / BM), 256, GEMM_SMEM>>>(x, mu1, inv1,
                                                           cb1h, cb1l, h1, K1, IN1);
    k_stats_fin<<<HD, 128>>>(HD, NPARTH, mu2, inv2);
    // layer 2 (writes h2 + partials)
    k_gemm<<<dim3(HD / BN, B_ROWS / BM), 256, GEMM_SMEM>>>(h1, mu2, inv2,
                                                           cb2h, cb2l, h2, K2, HD);
    k_stats_fin<<<HD, 128>>>(HD, NPARTH, mu3, inv3);
    // layer 3 + skip
    k_final<<<B_ROWS / 8, 256>>>(h2, mu3, inv3, cp3, x, sw, sb, out);
}